// round 1
// baseline (speedup 1.0000x reference)
#include <cuda_runtime.h>
#include <cuda_bf16.h>
#include <math.h>

// ---------------- problem constants (fixed by setup_inputs) ----------------
#define T_TOK   2048
#define DM      4096
#define NH      32
#define KVH     8
#define HD      128
#define QKV_N   6144          // 4096 + 2*8*128
#define K_OFF   4096
#define V_OFF   5120
#define CLIP    8.0f
#define SCALE   0.08838834764831845f   // 1/sqrt(128)

// seqlens 512,768,384,384 -> cu = 0,512,1280,1664,2048 ; 64-row qblocks: 8,12,6,6 (=32)

// ---------------- scratch (static device allocations) ----------------
__device__ float g_qkv[T_TOK * QKV_N];    // ~50 MB
__device__ float g_attn[T_TOK * DM];      // ~33 MB

// ============================================================================
// GEMM: C[M,N] = A[M,K] * B[N,K]^T   (A,B row-major, K contiguous)
// 128x128 tile, BK=16, 256 threads, 8x8 per thread (two 4x4 quadrants per axis)
// ============================================================================
__global__ void __launch_bounds__(256) gemm_nt_kernel(
    const float* __restrict__ A, const float* __restrict__ B,
    float* __restrict__ C, int M, int N, int K, int doClip)
{
    __shared__ float As[16][132];
    __shared__ float Bs[16][132];

    const int tid = threadIdx.x;
    const int m0 = blockIdx.y * 128;
    const int n0 = blockIdx.x * 128;
    const int ty = tid >> 4;     // 0..15
    const int tx = tid & 15;     // 0..15

    const float* Ab = A + (size_t)m0 * K;
    const float* Bb = B + (size_t)n0 * K;

    float acc[8][8];
#pragma unroll
    for (int i = 0; i < 8; i++)
#pragma unroll
        for (int j = 0; j < 8; j++) acc[i][j] = 0.0f;

    for (int k0 = 0; k0 < K; k0 += 16) {
        // load 128x16 tiles of A and B (transposed into smem: [k][m])
#pragma unroll
        for (int i = 0; i < 2; i++) {
            int id  = tid + i * 256;          // 0..511
            int row = id >> 2;                // 0..127
            int c4  = (id & 3) << 2;          // 0,4,8,12
            float4 va = *(const float4*)(Ab + (size_t)row * K + k0 + c4);
            As[c4 + 0][row] = va.x; As[c4 + 1][row] = va.y;
            As[c4 + 2][row] = va.z; As[c4 + 3][row] = va.w;
            float4 vb = *(const float4*)(Bb + (size_t)row * K + k0 + c4);
            Bs[c4 + 0][row] = vb.x; Bs[c4 + 1][row] = vb.y;
            Bs[c4 + 2][row] = vb.z; Bs[c4 + 3][row] = vb.w;
        }
        __syncthreads();

#pragma unroll
        for (int k = 0; k < 16; k++) {
            float a[8], b[8];
            *(float4*)&a[0] = *(const float4*)&As[k][ty * 4];
            *(float4*)&a[4] = *(const float4*)&As[k][ty * 4 + 64];
            *(float4*)&b[0] = *(const float4*)&Bs[k][tx * 4];
            *(float4*)&b[4] = *(const float4*)&Bs[k][tx * 4 + 64];
#pragma unroll
            for (int i = 0; i < 8; i++)
#pragma unroll
                for (int j = 0; j < 8; j++)
                    acc[i][j] = fmaf(a[i], b[j], acc[i][j]);
        }
        __syncthreads();
    }

    // epilogue
#pragma unroll
    for (int ih = 0; ih < 2; ih++) {
#pragma unroll
        for (int i = 0; i < 4; i++) {
            int m = m0 + ih * 64 + ty * 4 + i;
            float* cp = C + (size_t)m * N + n0;
#pragma unroll
            for (int jh = 0; jh < 2; jh++) {
                float4 v;
                v.x = acc[ih * 4 + i][jh * 4 + 0];
                v.y = acc[ih * 4 + i][jh * 4 + 1];
                v.z = acc[ih * 4 + i][jh * 4 + 2];
                v.w = acc[ih * 4 + i][jh * 4 + 3];
                if (doClip) {
                    v.x = fminf(CLIP, fmaxf(-CLIP, v.x));
                    v.y = fminf(CLIP, fmaxf(-CLIP, v.y));
                    v.z = fminf(CLIP, fmaxf(-CLIP, v.z));
                    v.w = fminf(CLIP, fmaxf(-CLIP, v.w));
                }
                *(float4*)(cp + jh * 64 + tx * 4) = v;
            }
        }
    }
}

// ============================================================================
// RoPE in-place on g_qkv: heads 0..31 = Q, 32..39 = K
// grid(T, 10), block(256): 4 heads per block, 64 dims each
// ============================================================================
__global__ void __launch_bounds__(256) rope_kernel(
    float* __restrict__ qkv, const float* __restrict__ cs, const float* __restrict__ sn)
{
    int t = blockIdx.x;
    int head = blockIdx.y * 4 + (threadIdx.x >> 6);   // 0..39
    int d = threadIdx.x & 63;
    float c = cs[t * 64 + d];
    float s = sn[t * 64 + d];
    size_t base = (head < NH)
        ? (size_t)t * QKV_N + head * HD
        : (size_t)t * QKV_N + K_OFF + (head - NH) * HD;
    float x1 = qkv[base + d];
    float x2 = qkv[base + 64 + d];
    qkv[base + d]      = x1 * c - x2 * s;
    qkv[base + 64 + d] = x2 * c + x1 * s;
}

// ============================================================================
// Flash attention: one block per (qblock, head). BQ=BK=64, D=128, 256 threads.
// Qs,Ks stored d-major [128][68]; Vs row-major [64][128]; S [64][68].
// QK phase: 16x16 threads, 4x4 scores each. Softmax/PV: thread=(row=tid/4, q=tid%4),
// thread owns d = q*4 + 16*i + l (8 float4 stripes).
// ============================================================================
#define ATT_SMEM_FLOATS (128*68 + 128*68 + 64*128 + 64*68)

__global__ void __launch_bounds__(256) attn_kernel(
    const float* __restrict__ qkv, float* __restrict__ out)
{
    extern __shared__ float sm[];
    float* Qs = sm;                 // [128][68]
    float* Ks = Qs + 128 * 68;      // [128][68]
    float* Vs = Ks + 128 * 68;      // [64][128]
    float* Ss = Vs + 64 * 128;      // [64][68]

    const int tid = threadIdx.x;
    const int h   = blockIdx.y;
    const int qb  = blockIdx.x;

    int seq, qb_local;
    if      (qb < 8)  { seq = 0; qb_local = qb; }
    else if (qb < 20) { seq = 1; qb_local = qb - 8; }
    else if (qb < 26) { seq = 2; qb_local = qb - 20; }
    else              { seq = 3; qb_local = qb - 26; }
    const int cu[4] = {0, 512, 1280, 1664};
    const int seq_start = cu[seq];
    const int q_start = seq_start + qb_local * 64;
    const int kh = h >> 2;

    const int ty = tid >> 4, tx = tid & 15;     // QK-phase mapping
    const int row = tid >> 2, q = tid & 3;      // softmax/PV mapping

    // load Q tile (d-major)
    {
        size_t qbase = (size_t)q_start * QKV_N + (size_t)h * HD;
#pragma unroll
        for (int i = 0; i < 8; i++) {
            int id = tid + i * 256;          // 0..2047
            int r  = id >> 5;                // token row 0..63
            int d4 = (id & 31) << 2;
            float4 v = *(const float4*)(qkv + qbase + (size_t)r * QKV_N + d4);
            Qs[(d4 + 0) * 68 + r] = v.x;
            Qs[(d4 + 1) * 68 + r] = v.y;
            Qs[(d4 + 2) * 68 + r] = v.z;
            Qs[(d4 + 3) * 68 + r] = v.w;
        }
    }

    float m_run = -INFINITY;
    float l_run = 0.0f;
    float4 o[8];
#pragma unroll
    for (int i = 0; i < 8; i++) o[i] = make_float4(0.f, 0.f, 0.f, 0.f);

    __syncthreads();

    for (int kb = 0; kb <= qb_local; kb++) {
        // ---- load K (d-major) and V (row-major) tiles ----
        size_t kbase = (size_t)(seq_start + kb * 64) * QKV_N + K_OFF + (size_t)kh * HD;
        size_t vbase = (size_t)(seq_start + kb * 64) * QKV_N + V_OFF + (size_t)kh * HD;
#pragma unroll
        for (int i = 0; i < 8; i++) {
            int id = tid + i * 256;
            int r  = id >> 5;
            int d4 = (id & 31) << 2;
            float4 kv = *(const float4*)(qkv + kbase + (size_t)r * QKV_N + d4);
            Ks[(d4 + 0) * 68 + r] = kv.x;
            Ks[(d4 + 1) * 68 + r] = kv.y;
            Ks[(d4 + 2) * 68 + r] = kv.z;
            Ks[(d4 + 3) * 68 + r] = kv.w;
            float4 vv = *(const float4*)(qkv + vbase + (size_t)r * QKV_N + d4);
            *(float4*)&Vs[r * 128 + d4] = vv;
        }
        __syncthreads();

        // ---- S = Q K^T * scale (4x4 per thread) ----
        float s[4][4];
#pragma unroll
        for (int i = 0; i < 4; i++)
#pragma unroll
            for (int j = 0; j < 4; j++) s[i][j] = 0.0f;

#pragma unroll 4
        for (int k = 0; k < 128; k++) {
            float4 qv = *(const float4*)&Qs[k * 68 + ty * 4];
            float4 kv = *(const float4*)&Ks[k * 68 + tx * 4];
            float qa[4] = {qv.x, qv.y, qv.z, qv.w};
            float ka[4] = {kv.x, kv.y, kv.z, kv.w};
#pragma unroll
            for (int i = 0; i < 4; i++)
#pragma unroll
                for (int j = 0; j < 4; j++)
                    s[i][j] = fmaf(qa[i], ka[j], s[i][j]);
        }

        bool diag = (kb == qb_local);
#pragma unroll
        for (int i = 0; i < 4; i++) {
            int r = ty * 4 + i;
            float4 v;
            float vs[4];
#pragma unroll
            for (int j = 0; j < 4; j++) {
                float val = s[i][j] * SCALE;
                if (diag && (tx * 4 + j > r)) val = -1e30f;
                vs[j] = val;
            }
            v.x = vs[0]; v.y = vs[1]; v.z = vs[2]; v.w = vs[3];
            *(float4*)&Ss[r * 68 + tx * 4] = v;
        }
        __syncthreads();

        // ---- online softmax (4 threads per row) ----
        float lmax = -INFINITY;
#pragma unroll
        for (int jj = 0; jj < 16; jj++)
            lmax = fmaxf(lmax, Ss[row * 68 + q * 16 + jj]);
        lmax = fmaxf(lmax, __shfl_xor_sync(0xffffffffu, lmax, 1));
        lmax = fmaxf(lmax, __shfl_xor_sync(0xffffffffu, lmax, 2));
        float m_new = fmaxf(m_run, lmax);
        float alpha = __expf(m_run - m_new);

        float lsum = 0.0f;
#pragma unroll
        for (int jj = 0; jj < 16; jj++) {
            float p = __expf(Ss[row * 68 + q * 16 + jj] - m_new);
            Ss[row * 68 + q * 16 + jj] = p;
            lsum += p;
        }
        lsum += __shfl_xor_sync(0xffffffffu, lsum, 1);
        lsum += __shfl_xor_sync(0xffffffffu, lsum, 2);
        l_run = l_run * alpha + lsum;
        m_run = m_new;
        __syncthreads();

        // ---- rescale O, accumulate P*V ----
#pragma unroll
        for (int i = 0; i < 8; i++) {
            o[i].x *= alpha; o[i].y *= alpha; o[i].z *= alpha; o[i].w *= alpha;
        }
#pragma unroll 2
        for (int j = 0; j < 64; j++) {
            float p = Ss[row * 68 + j];
#pragma unroll
            for (int i = 0; i < 8; i++) {
                float4 vv = *(const float4*)&Vs[j * 128 + q * 4 + 16 * i];
                o[i].x = fmaf(p, vv.x, o[i].x);
                o[i].y = fmaf(p, vv.y, o[i].y);
                o[i].z = fmaf(p, vv.z, o[i].z);
                o[i].w = fmaf(p, vv.w, o[i].w);
            }
        }
        __syncthreads();
    }

    // ---- normalize and write ----
    float inv = 1.0f / l_run;
    size_t obase = (size_t)(q_start + row) * DM + (size_t)h * HD;
#pragma unroll
    for (int i = 0; i < 8; i++) {
        float4 v = o[i];
        v.x *= inv; v.y *= inv; v.z *= inv; v.w *= inv;
        *(float4*)(out + obase + q * 4 + 16 * i) = v;
    }
}

// ============================================================================
// launch
// ============================================================================
extern "C" void kernel_launch(void* const* d_in, const int* in_sizes, int n_in,
                              void* d_out, int out_size)
{
    const float* hs    = (const float*)d_in[0];
    const float* w_qkv = (const float*)d_in[1];
    const float* w_o   = (const float*)d_in[2];
    const float* cs    = (const float*)d_in[3];
    const float* sn    = (const float*)d_in[4];
    (void)in_sizes; (void)n_in;

    float* qkv_buf = nullptr;
    float* attn_buf = nullptr;
    cudaGetSymbolAddress((void**)&qkv_buf, g_qkv);
    cudaGetSymbolAddress((void**)&attn_buf, g_attn);

    // QKV projection + clip
    gemm_nt_kernel<<<dim3(QKV_N / 128, T_TOK / 128), 256>>>(
        hs, w_qkv, qkv_buf, T_TOK, QKV_N, DM, 1);

    // RoPE on Q and K
    rope_kernel<<<dim3(T_TOK, 10), 256>>>(qkv_buf, cs, sn);

    // attention
    static int smem_set = 0;
    size_t smem_bytes = ATT_SMEM_FLOATS * sizeof(float);
    if (!smem_set) {
        cudaFuncSetAttribute(attn_kernel,
                             cudaFuncAttributeMaxDynamicSharedMemorySize,
                             (int)smem_bytes);
        smem_set = 1;
    }
    attn_kernel<<<dim3(32, NH), 256, smem_bytes>>>(qkv_buf, attn_buf);

    // output projection
    gemm_nt_kernel<<<dim3(DM / 128, T_TOK / 128), 256>>>(
        attn_buf, w_o, (float*)d_out, T_TOK, DM, DM, 0);
}

// round 3
// speedup vs baseline: 2.2945x; 2.2945x over previous
#include <cuda_runtime.h>
#include <cuda_bf16.h>
#include <math.h>
#include <cstdint>

// ---------------- problem constants (fixed by setup_inputs) ----------------
#define T_TOK   2048
#define DM      4096
#define NH      32
#define KVH     8
#define HD      128
#define QKV_N   6144          // 4096 + 2*8*128
#define K_OFF   4096
#define V_OFF   5120
#define CLIPV   8.0f
#define SCALE   0.08838834764831845f   // 1/sqrt(128)
#define KTOT    4096

// ---------------- scratch ----------------
__device__ float g_qkv[T_TOK * QKV_N];
__device__ float g_attn[T_TOK * DM];
__device__ __align__(16) __nv_bfloat16 g_ahi[T_TOK * DM];
__device__ __align__(16) __nv_bfloat16 g_alo[T_TOK * DM];
__device__ __align__(16) __nv_bfloat16 g_bhi[QKV_N * DM];
__device__ __align__(16) __nv_bfloat16 g_blo[QKV_N * DM];

// ============================ PTX helpers ============================
__device__ __forceinline__ uint32_t smem_u32_of(const void* p) {
    uint32_t a;
    asm("{ .reg .u64 t; cvta.to.shared.u64 t, %1; cvt.u32.u64 %0, t; }"
        : "=r"(a) : "l"(p));
    return a;
}
__device__ __forceinline__ void cp_async16(uint32_t dst, const void* src) {
    asm volatile("cp.async.cg.shared.global [%0], [%1], 16;" :: "r"(dst), "l"(src));
}
__device__ __forceinline__ void cp_commit() {
    asm volatile("cp.async.commit_group;" ::: "memory");
}
template<int N> __device__ __forceinline__ void cp_wait() {
    asm volatile("cp.async.wait_group %0;" :: "n"(N) : "memory");
}
__device__ __forceinline__ void ldsm4(uint32_t (&r)[4], uint32_t addr) {
    asm volatile("ldmatrix.sync.aligned.m8n8.x4.shared.b16 {%0,%1,%2,%3}, [%4];"
        : "=r"(r[0]), "=r"(r[1]), "=r"(r[2]), "=r"(r[3]) : "r"(addr));
}
__device__ __forceinline__ void mma16816(float (&d)[4], const uint32_t (&a)[4],
                                         const uint32_t* b) {
    asm volatile("mma.sync.aligned.m16n8k16.row.col.f32.bf16.bf16.f32 "
        "{%0,%1,%2,%3}, {%4,%5,%6,%7}, {%8,%9}, {%0,%1,%2,%3};"
        : "+f"(d[0]), "+f"(d[1]), "+f"(d[2]), "+f"(d[3])
        : "r"(a[0]), "r"(a[1]), "r"(a[2]), "r"(a[3]), "r"(b[0]), "r"(b[1]));
}

// ============================================================================
// split fp32 -> bf16 hi/lo
// ============================================================================
__global__ void __launch_bounds__(256) split_kernel(
    const float* __restrict__ in, __nv_bfloat16* __restrict__ hi,
    __nv_bfloat16* __restrict__ lo, int n4)
{
    int i = blockIdx.x * 256 + threadIdx.x;
    if (i >= n4) return;
    float4 v = ((const float4*)in)[i];
    float a[4] = {v.x, v.y, v.z, v.w};
    __nv_bfloat16 h[4], l[4];
#pragma unroll
    for (int j = 0; j < 4; j++) {
        h[j] = __float2bfloat16(a[j]);
        l[j] = __float2bfloat16(a[j] - __bfloat162float(h[j]));
    }
    ((uint2*)hi)[i] = *(uint2*)h;
    ((uint2*)lo)[i] = *(uint2*)l;
}

// ============================================================================
// HMMA GEMM: C[M,N] = A[M,K] * B[N,K]^T, split-bf16 3-pass.
// CTA 128x128, BK=64, 8 warps (2x4), warp tile 64x32 (4x4 m16n8k16 atoms).
// Smem per stage: Ahi|Alo|Bhi|Blo, each [128 rows][64 bf16] (128B rows,
// 16B chunks XOR-swizzled: chunk' = chunk ^ (row&7)). 2 stages = 128KB.
// ============================================================================
#define STAGE_BYTES 65536
#define GEMM_SMEM   (2 * STAGE_BYTES)
#define NCHUNK      (KTOT / 64)

__global__ void __launch_bounds__(256, 1) gemm_tc_kernel(
    const __nv_bfloat16* __restrict__ Ahi, const __nv_bfloat16* __restrict__ Alo,
    const __nv_bfloat16* __restrict__ Bhi, const __nv_bfloat16* __restrict__ Blo,
    float* __restrict__ C, int Ntot, int doClip)
{
    extern __shared__ char smem[];
    const uint32_t sb = smem_u32_of(smem);
    const int tid  = threadIdx.x;
    const int wid  = tid >> 5;
    const int lane = tid & 31;
    const int warp_m = wid >> 2;      // 0..1
    const int warp_n = wid & 3;       // 0..3
    const int m0 = blockIdx.y * 128;
    const int n0 = blockIdx.x * 128;

    const __nv_bfloat16* srcs[4];
    srcs[0] = Ahi; srcs[1] = Alo; srcs[2] = Bhi; srcs[3] = Blo;

    // ldmatrix per-lane geometry
    const int g = lane >> 3, r = lane & 7;
    const int a_row  = warp_m * 64 + (g & 1) * 8 + r;   // + mi*16
    const int a_csel = g >> 1;
    const int b_row  = warp_n * 32 + (g >> 1) * 8 + r;  // + j*16
    const int b_csel = g & 1;

    float acc[4][4][4];
#pragma unroll
    for (int i = 0; i < 4; i++)
#pragma unroll
        for (int j = 0; j < 4; j++)
#pragma unroll
            for (int k = 0; k < 4; k++) acc[i][j][k] = 0.0f;

#define LOAD_CHUNK(cc, ss) do { \
    const int k0_ = (cc) * 64; \
    const uint32_t sbase_ = sb + (ss) * STAGE_BYTES; \
    _Pragma("unroll") \
    for (int t_ = 0; t_ < 16; t_++) { \
        int id_ = tid + t_ * 256; \
        int tile_ = id_ >> 10; \
        int w_ = id_ & 1023; \
        int mrow_ = w_ >> 3; \
        int cch_ = w_ & 7; \
        int grow_ = (tile_ < 2) ? (m0 + mrow_) : (n0 + mrow_); \
        const void* src_ = srcs[tile_] + (size_t)grow_ * KTOT + k0_ + cch_ * 8; \
        uint32_t dst_ = sbase_ + tile_ * 16384 + mrow_ * 128 + ((cch_ ^ (mrow_ & 7)) << 4); \
        cp_async16(dst_, src_); \
    } \
    cp_commit(); \
} while (0)

    LOAD_CHUNK(0, 0);
    LOAD_CHUNK(1, 1);

    for (int c = 0; c < NCHUNK; c++) {
        if (c < NCHUNK - 2) cp_wait<1>(); else cp_wait<0>();
        __syncthreads();

        const uint32_t st = sb + (c & 1) * STAGE_BYTES;
#pragma unroll
        for (int s = 0; s < 4; s++) {
            uint32_t a_hi[4][4], a_lo[4][4];
#pragma unroll
            for (int mi = 0; mi < 4; mi++) {
                int m = a_row + mi * 16;
                uint32_t off = (uint32_t)(m * 128) +
                               ((((s << 1) + a_csel) ^ (m & 7)) << 4);
                ldsm4(a_hi[mi], st + off);
                ldsm4(a_lo[mi], st + 16384 + off);
            }
            uint32_t b_hi[2][4], b_lo[2][4];
#pragma unroll
            for (int j = 0; j < 2; j++) {
                int n = b_row + j * 16;
                uint32_t off = (uint32_t)(n * 128) +
                               ((((s << 1) + b_csel) ^ (n & 7)) << 4);
                ldsm4(b_hi[j], st + 32768 + off);
                ldsm4(b_lo[j], st + 49152 + off);
            }
#pragma unroll
            for (int mi = 0; mi < 4; mi++) {
#pragma unroll
                for (int nj = 0; nj < 4; nj++) {
                    const uint32_t* bh = &b_hi[nj >> 1][(nj & 1) * 2];
                    const uint32_t* bl = &b_lo[nj >> 1][(nj & 1) * 2];
                    mma16816(acc[mi][nj], a_hi[mi], bh);
                    mma16816(acc[mi][nj], a_hi[mi], bl);
                    mma16816(acc[mi][nj], a_lo[mi], bh);
                }
            }
        }
        __syncthreads();
        if (c + 2 < NCHUNK) LOAD_CHUNK(c + 2, c & 1);
    }

    // epilogue: direct float2 stores
    const int qrow = lane >> 2;
    const int qcol = (lane & 3) * 2;
#pragma unroll
    for (int mi = 0; mi < 4; mi++) {
#pragma unroll
        for (int nj = 0; nj < 4; nj++) {
            int m = m0 + warp_m * 64 + mi * 16 + qrow;
            int n = n0 + warp_n * 32 + nj * 8 + qcol;
            float v0 = acc[mi][nj][0], v1 = acc[mi][nj][1];
            float v2 = acc[mi][nj][2], v3 = acc[mi][nj][3];
            if (doClip) {
                v0 = fminf(CLIPV, fmaxf(-CLIPV, v0));
                v1 = fminf(CLIPV, fmaxf(-CLIPV, v1));
                v2 = fminf(CLIPV, fmaxf(-CLIPV, v2));
                v3 = fminf(CLIPV, fmaxf(-CLIPV, v3));
            }
            float2 p0 = make_float2(v0, v1);
            float2 p1 = make_float2(v2, v3);
            *(float2*)(C + (size_t)m * Ntot + n) = p0;
            *(float2*)(C + (size_t)(m + 8) * Ntot + n) = p1;
        }
    }
}

// ============================================================================
// RoPE in-place on g_qkv: heads 0..31 = Q, 32..39 = K
// ============================================================================
__global__ void __launch_bounds__(256) rope_kernel(
    float* __restrict__ qkv, const float* __restrict__ cs, const float* __restrict__ sn)
{
    int t = blockIdx.x;
    int head = blockIdx.y * 4 + (threadIdx.x >> 6);   // 0..39
    int d = threadIdx.x & 63;
    float c = cs[t * 64 + d];
    float s = sn[t * 64 + d];
    size_t base = (head < NH)
        ? (size_t)t * QKV_N + head * HD
        : (size_t)t * QKV_N + K_OFF + (head - NH) * HD;
    float x1 = qkv[base + d];
    float x2 = qkv[base + 64 + d];
    qkv[base + d]      = x1 * c - x2 * s;
    qkv[base + 64 + d] = x2 * c + x1 * s;
}

// ============================================================================
// Flash attention (proven R1 version)
// ============================================================================
#define ATT_SMEM_FLOATS (128*68 + 128*68 + 64*128 + 64*68)

__global__ void __launch_bounds__(256) attn_kernel(
    const float* __restrict__ qkv, float* __restrict__ out)
{
    extern __shared__ float sm[];
    float* Qs = sm;                 // [128][68]
    float* Ks = Qs + 128 * 68;      // [128][68]
    float* Vs = Ks + 128 * 68;      // [64][128]
    float* Ss = Vs + 64 * 128;      // [64][68]

    const int tid = threadIdx.x;
    const int h   = blockIdx.y;
    const int qb  = blockIdx.x;

    int seq, qb_local;
    if      (qb < 8)  { seq = 0; qb_local = qb; }
    else if (qb < 20) { seq = 1; qb_local = qb - 8; }
    else if (qb < 26) { seq = 2; qb_local = qb - 20; }
    else              { seq = 3; qb_local = qb - 26; }
    const int cu[4] = {0, 512, 1280, 1664};
    const int seq_start = cu[seq];
    const int q_start = seq_start + qb_local * 64;
    const int kh = h >> 2;

    const int ty = tid >> 4, tx = tid & 15;
    const int row = tid >> 2, q = tid & 3;

    {
        size_t qbase = (size_t)q_start * QKV_N + (size_t)h * HD;
#pragma unroll
        for (int i = 0; i < 8; i++) {
            int id = tid + i * 256;
            int rr = id >> 5;
            int d4 = (id & 31) << 2;
            float4 v = *(const float4*)(qkv + qbase + (size_t)rr * QKV_N + d4);
            Qs[(d4 + 0) * 68 + rr] = v.x;
            Qs[(d4 + 1) * 68 + rr] = v.y;
            Qs[(d4 + 2) * 68 + rr] = v.z;
            Qs[(d4 + 3) * 68 + rr] = v.w;
        }
    }

    float m_run = -INFINITY;
    float l_run = 0.0f;
    float4 o[8];
#pragma unroll
    for (int i = 0; i < 8; i++) o[i] = make_float4(0.f, 0.f, 0.f, 0.f);

    __syncthreads();

    for (int kb = 0; kb <= qb_local; kb++) {
        size_t kbase = (size_t)(seq_start + kb * 64) * QKV_N + K_OFF + (size_t)kh * HD;
        size_t vbase = (size_t)(seq_start + kb * 64) * QKV_N + V_OFF + (size_t)kh * HD;
#pragma unroll
        for (int i = 0; i < 8; i++) {
            int id = tid + i * 256;
            int rr = id >> 5;
            int d4 = (id & 31) << 2;
            float4 kv = *(const float4*)(qkv + kbase + (size_t)rr * QKV_N + d4);
            Ks[(d4 + 0) * 68 + rr] = kv.x;
            Ks[(d4 + 1) * 68 + rr] = kv.y;
            Ks[(d4 + 2) * 68 + rr] = kv.z;
            Ks[(d4 + 3) * 68 + rr] = kv.w;
            float4 vv = *(const float4*)(qkv + vbase + (size_t)rr * QKV_N + d4);
            *(float4*)&Vs[rr * 128 + d4] = vv;
        }
        __syncthreads();

        float s[4][4];
#pragma unroll
        for (int i = 0; i < 4; i++)
#pragma unroll
            for (int j = 0; j < 4; j++) s[i][j] = 0.0f;

#pragma unroll 4
        for (int k = 0; k < 128; k++) {
            float4 qv = *(const float4*)&Qs[k * 68 + ty * 4];
            float4 kv = *(const float4*)&Ks[k * 68 + tx * 4];
            float qa[4] = {qv.x, qv.y, qv.z, qv.w};
            float ka[4] = {kv.x, kv.y, kv.z, kv.w};
#pragma unroll
            for (int i = 0; i < 4; i++)
#pragma unroll
                for (int j = 0; j < 4; j++)
                    s[i][j] = fmaf(qa[i], ka[j], s[i][j]);
        }

        bool diag = (kb == qb_local);
#pragma unroll
        for (int i = 0; i < 4; i++) {
            int rr = ty * 4 + i;
            float4 v;
            float vs[4];
#pragma unroll
            for (int j = 0; j < 4; j++) {
                float val = s[i][j] * SCALE;
                if (diag && (tx * 4 + j > rr)) val = -1e30f;
                vs[j] = val;
            }
            v.x = vs[0]; v.y = vs[1]; v.z = vs[2]; v.w = vs[3];
            *(float4*)&Ss[rr * 68 + tx * 4] = v;
        }
        __syncthreads();

        float lmax = -INFINITY;
#pragma unroll
        for (int jj = 0; jj < 16; jj++)
            lmax = fmaxf(lmax, Ss[row * 68 + q * 16 + jj]);
        lmax = fmaxf(lmax, __shfl_xor_sync(0xffffffffu, lmax, 1));
        lmax = fmaxf(lmax, __shfl_xor_sync(0xffffffffu, lmax, 2));
        float m_new = fmaxf(m_run, lmax);
        float alpha = __expf(m_run - m_new);

        float lsum = 0.0f;
#pragma unroll
        for (int jj = 0; jj < 16; jj++) {
            float p = __expf(Ss[row * 68 + q * 16 + jj] - m_new);
            Ss[row * 68 + q * 16 + jj] = p;
            lsum += p;
        }
        lsum += __shfl_xor_sync(0xffffffffu, lsum, 1);
        lsum += __shfl_xor_sync(0xffffffffu, lsum, 2);
        l_run = l_run * alpha + lsum;
        m_run = m_new;
        __syncthreads();

#pragma unroll
        for (int i = 0; i < 8; i++) {
            o[i].x *= alpha; o[i].y *= alpha; o[i].z *= alpha; o[i].w *= alpha;
        }
#pragma unroll 2
        for (int j = 0; j < 64; j++) {
            float p = Ss[row * 68 + j];
#pragma unroll
            for (int i = 0; i < 8; i++) {
                float4 vv = *(const float4*)&Vs[j * 128 + q * 4 + 16 * i];
                o[i].x = fmaf(p, vv.x, o[i].x);
                o[i].y = fmaf(p, vv.y, o[i].y);
                o[i].z = fmaf(p, vv.z, o[i].z);
                o[i].w = fmaf(p, vv.w, o[i].w);
            }
        }
        __syncthreads();
    }

    float inv = 1.0f / l_run;
    size_t obase = (size_t)(q_start + row) * DM + (size_t)h * HD;
#pragma unroll
    for (int i = 0; i < 8; i++) {
        float4 v = o[i];
        v.x *= inv; v.y *= inv; v.z *= inv; v.w *= inv;
        *(float4*)(out + obase + q * 4 + 16 * i) = v;
    }
}

// ============================================================================
// launch
// ============================================================================
extern "C" void kernel_launch(void* const* d_in, const int* in_sizes, int n_in,
                              void* d_out, int out_size)
{
    const float* hs    = (const float*)d_in[0];
    const float* w_qkv = (const float*)d_in[1];
    const float* w_o   = (const float*)d_in[2];
    const float* cs    = (const float*)d_in[3];
    const float* sn    = (const float*)d_in[4];
    (void)in_sizes; (void)n_in;

    float* qkv_buf = nullptr;
    float* attn_buf = nullptr;
    __nv_bfloat16 *ahi, *alo, *bhi, *blo;
    cudaGetSymbolAddress((void**)&qkv_buf, g_qkv);
    cudaGetSymbolAddress((void**)&attn_buf, g_attn);
    cudaGetSymbolAddress((void**)&ahi, g_ahi);
    cudaGetSymbolAddress((void**)&alo, g_alo);
    cudaGetSymbolAddress((void**)&bhi, g_bhi);
    cudaGetSymbolAddress((void**)&blo, g_blo);

    static int attr_set = 0;
    if (!attr_set) {
        cudaFuncSetAttribute(attn_kernel, cudaFuncAttributeMaxDynamicSharedMemorySize,
                             (int)(ATT_SMEM_FLOATS * sizeof(float)));
        cudaFuncSetAttribute(gemm_tc_kernel, cudaFuncAttributeMaxDynamicSharedMemorySize,
                             GEMM_SMEM);
        attr_set = 1;
    }

    // split inputs to bf16 hi/lo
    split_kernel<<<(T_TOK * DM / 4) / 256, 256>>>(hs, ahi, alo, T_TOK * DM / 4);
    split_kernel<<<(QKV_N * DM / 4) / 256, 256>>>(w_qkv, bhi, blo, QKV_N * DM / 4);

    // QKV projection + clip (tensor cores)
    gemm_tc_kernel<<<dim3(QKV_N / 128, T_TOK / 128), 256, GEMM_SMEM>>>(
        ahi, alo, bhi, blo, qkv_buf, QKV_N, 1);

    // RoPE on Q and K
    rope_kernel<<<dim3(T_TOK, 10), 256>>>(qkv_buf, cs, sn);

    // attention
    attn_kernel<<<dim3(32, NH), 256, ATT_SMEM_FLOATS * sizeof(float)>>>(qkv_buf, attn_buf);

    // split attn output + w_o, then output projection
    split_kernel<<<(T_TOK * DM / 4) / 256, 256>>>(attn_buf, ahi, alo, T_TOK * DM / 4);
    split_kernel<<<(DM * DM / 4) / 256, 256>>>(w_o, bhi, blo, DM * DM / 4);

    gemm_tc_kernel<<<dim3(DM / 128, T_TOK / 128), 256, GEMM_SMEM>>>(
        ahi, alo, bhi, blo, (float*)d_out, DM, 0);
}

// round 4
// speedup vs baseline: 2.3120x; 1.0076x over previous
#include <cuda_runtime.h>
#include <cuda_bf16.h>
#include <math.h>
#include <cstdint>

// ---------------- problem constants (fixed by setup_inputs) ----------------
#define T_TOK   2048
#define DM      4096
#define NH      32
#define KVH     8
#define HD      128
#define QKV_N   6144          // 4096 + 2*8*128
#define K_OFF   4096
#define V_OFF   5120
#define CLIPV   8.0f
#define SCALE   0.08838834764831845f   // 1/sqrt(128)
#define KTOT    4096

// ---------------- scratch ----------------
__device__ float g_qkv[T_TOK * QKV_N];
__device__ __align__(16) __nv_bfloat16 g_ahi[T_TOK * DM];
__device__ __align__(16) __nv_bfloat16 g_alo[T_TOK * DM];
__device__ __align__(16) __nv_bfloat16 g_bhi[QKV_N * DM];
__device__ __align__(16) __nv_bfloat16 g_blo[QKV_N * DM];

// ============================ PTX helpers ============================
__device__ __forceinline__ uint32_t smem_u32_of(const void* p) {
    uint32_t a;
    asm("{ .reg .u64 t; cvta.to.shared.u64 t, %1; cvt.u32.u64 %0, t; }"
        : "=r"(a) : "l"(p));
    return a;
}
__device__ __forceinline__ void cp_async16(uint32_t dst, const void* src) {
    asm volatile("cp.async.cg.shared.global [%0], [%1], 16;" :: "r"(dst), "l"(src));
}
__device__ __forceinline__ void cp_commit() {
    asm volatile("cp.async.commit_group;" ::: "memory");
}
template<int N> __device__ __forceinline__ void cp_wait() {
    asm volatile("cp.async.wait_group %0;" :: "n"(N) : "memory");
}
__device__ __forceinline__ void ldsm4(uint32_t (&r)[4], uint32_t addr) {
    asm volatile("ldmatrix.sync.aligned.m8n8.x4.shared.b16 {%0,%1,%2,%3}, [%4];"
        : "=r"(r[0]), "=r"(r[1]), "=r"(r[2]), "=r"(r[3]) : "r"(addr));
}
__device__ __forceinline__ void mma16816(float (&d)[4], const uint32_t (&a)[4],
                                         const uint32_t* b) {
    asm volatile("mma.sync.aligned.m16n8k16.row.col.f32.bf16.bf16.f32 "
        "{%0,%1,%2,%3}, {%4,%5,%6,%7}, {%8,%9}, {%0,%1,%2,%3};"
        : "+f"(d[0]), "+f"(d[1]), "+f"(d[2]), "+f"(d[3])
        : "r"(a[0]), "r"(a[1]), "r"(a[2]), "r"(a[3]), "r"(b[0]), "r"(b[1]));
}

// ============================================================================
// split fp32 -> bf16 hi/lo
// ============================================================================
__global__ void __launch_bounds__(256) split_kernel(
    const float* __restrict__ in, __nv_bfloat16* __restrict__ hi,
    __nv_bfloat16* __restrict__ lo, int n4)
{
    int i = blockIdx.x * 256 + threadIdx.x;
    if (i >= n4) return;
    float4 v = ((const float4*)in)[i];
    float a[4] = {v.x, v.y, v.z, v.w};
    __nv_bfloat16 h[4], l[4];
#pragma unroll
    for (int j = 0; j < 4; j++) {
        h[j] = __float2bfloat16(a[j]);
        l[j] = __float2bfloat16(a[j] - __bfloat162float(h[j]));
    }
    ((uint2*)hi)[i] = *(uint2*)h;
    ((uint2*)lo)[i] = *(uint2*)l;
}

// ============================================================================
// HMMA GEMM: C[M,N] = A[M,K] * B[N,K]^T, split-bf16 3-pass.
// CTA 128x128, BK=64, 8 warps (2x4), warp tile 64x32 (4x4 m16n8k16 atoms).
// Smem per stage: Ahi|Alo|Bhi|Blo, each [128 rows][64 bf16] (128B rows,
// 16B chunks XOR-swizzled: chunk' = chunk ^ (row&7)). 3 stages = 192KB.
// One __syncthreads per chunk; cp.async for c+2 issued right after barrier.
// ============================================================================
#define STAGE_BYTES 65536
#define NSTAGE      3
#define GEMM_SMEM   (NSTAGE * STAGE_BYTES)
#define NCHUNK      (KTOT / 64)

__global__ void __launch_bounds__(256, 1) gemm_tc_kernel(
    const __nv_bfloat16* __restrict__ Ahi, const __nv_bfloat16* __restrict__ Alo,
    const __nv_bfloat16* __restrict__ Bhi, const __nv_bfloat16* __restrict__ Blo,
    float* __restrict__ C, int Ntot, int doClip)
{
    extern __shared__ char smem[];
    const uint32_t sb = smem_u32_of(smem);
    const int tid  = threadIdx.x;
    const int wid  = tid >> 5;
    const int lane = tid & 31;
    const int warp_m = wid >> 2;      // 0..1
    const int warp_n = wid & 3;       // 0..3
    const int m0 = blockIdx.y * 128;
    const int n0 = blockIdx.x * 128;

    const __nv_bfloat16* srcs[4];
    srcs[0] = Ahi; srcs[1] = Alo; srcs[2] = Bhi; srcs[3] = Blo;

    // ldmatrix per-lane geometry
    const int g = lane >> 3, r = lane & 7;
    const int a_row  = warp_m * 64 + (g & 1) * 8 + r;   // + mi*16
    const int a_csel = g >> 1;
    const int b_row  = warp_n * 32 + (g >> 1) * 8 + r;  // + j*16
    const int b_csel = g & 1;

    float acc[4][4][4];
#pragma unroll
    for (int i = 0; i < 4; i++)
#pragma unroll
        for (int j = 0; j < 4; j++)
#pragma unroll
            for (int k = 0; k < 4; k++) acc[i][j][k] = 0.0f;

#define LOAD_CHUNK(cc, ss) do { \
    const int k0_ = (cc) * 64; \
    const uint32_t sbase_ = sb + (ss) * STAGE_BYTES; \
    _Pragma("unroll") \
    for (int t_ = 0; t_ < 16; t_++) { \
        int id_ = tid + t_ * 256; \
        int tile_ = id_ >> 10; \
        int w_ = id_ & 1023; \
        int mrow_ = w_ >> 3; \
        int cch_ = w_ & 7; \
        int grow_ = (tile_ < 2) ? (m0 + mrow_) : (n0 + mrow_); \
        const void* src_ = srcs[tile_] + (size_t)grow_ * KTOT + k0_ + cch_ * 8; \
        uint32_t dst_ = sbase_ + tile_ * 16384 + mrow_ * 128 + ((cch_ ^ (mrow_ & 7)) << 4); \
        cp_async16(dst_, src_); \
    } \
    cp_commit(); \
} while (0)

    LOAD_CHUNK(0, 0);
    LOAD_CHUNK(1, 1);

    int stage = 0;      // c % 3
    int lstage = 2;     // (c+2) % 3
    for (int c = 0; c < NCHUNK; c++) {
        if (c == NCHUNK - 1) cp_wait<0>(); else cp_wait<1>();
        __syncthreads();

        if (c + 2 < NCHUNK) LOAD_CHUNK(c + 2, lstage);

        const uint32_t st = sb + stage * STAGE_BYTES;
#pragma unroll
        for (int s = 0; s < 4; s++) {
            uint32_t a_hi[4][4], a_lo[4][4];
#pragma unroll
            for (int mi = 0; mi < 4; mi++) {
                int m = a_row + mi * 16;
                uint32_t off = (uint32_t)(m * 128) +
                               ((((s << 1) + a_csel) ^ (m & 7)) << 4);
                ldsm4(a_hi[mi], st + off);
                ldsm4(a_lo[mi], st + 16384 + off);
            }
            uint32_t b_hi[2][4], b_lo[2][4];
#pragma unroll
            for (int j = 0; j < 2; j++) {
                int n = b_row + j * 16;
                uint32_t off = (uint32_t)(n * 128) +
                               ((((s << 1) + b_csel) ^ (n & 7)) << 4);
                ldsm4(b_hi[j], st + 32768 + off);
                ldsm4(b_lo[j], st + 49152 + off);
            }
#pragma unroll
            for (int mi = 0; mi < 4; mi++) {
#pragma unroll
                for (int nj = 0; nj < 4; nj++) {
                    const uint32_t* bh = &b_hi[nj >> 1][(nj & 1) * 2];
                    const uint32_t* bl = &b_lo[nj >> 1][(nj & 1) * 2];
                    mma16816(acc[mi][nj], a_hi[mi], bh);
                    mma16816(acc[mi][nj], a_hi[mi], bl);
                    mma16816(acc[mi][nj], a_lo[mi], bh);
                }
            }
        }
        stage = (stage == 2) ? 0 : stage + 1;
        lstage = (lstage == 2) ? 0 : lstage + 1;
    }

    // epilogue: direct float2 stores
    const int qrow = lane >> 2;
    const int qcol = (lane & 3) * 2;
#pragma unroll
    for (int mi = 0; mi < 4; mi++) {
#pragma unroll
        for (int nj = 0; nj < 4; nj++) {
            int m = m0 + warp_m * 64 + mi * 16 + qrow;
            int n = n0 + warp_n * 32 + nj * 8 + qcol;
            float v0 = acc[mi][nj][0], v1 = acc[mi][nj][1];
            float v2 = acc[mi][nj][2], v3 = acc[mi][nj][3];
            if (doClip) {
                v0 = fminf(CLIPV, fmaxf(-CLIPV, v0));
                v1 = fminf(CLIPV, fmaxf(-CLIPV, v1));
                v2 = fminf(CLIPV, fmaxf(-CLIPV, v2));
                v3 = fminf(CLIPV, fmaxf(-CLIPV, v3));
            }
            float2 p0 = make_float2(v0, v1);
            float2 p1 = make_float2(v2, v3);
            *(float2*)(C + (size_t)m * Ntot + n) = p0;
            *(float2*)(C + (size_t)(m + 8) * Ntot + n) = p1;
        }
    }
}

// ============================================================================
// RoPE in-place on g_qkv: heads 0..31 = Q, 32..39 = K
// ============================================================================
__global__ void __launch_bounds__(256) rope_kernel(
    float* __restrict__ qkv, const float* __restrict__ cs, const float* __restrict__ sn)
{
    int t = blockIdx.x;
    int head = blockIdx.y * 4 + (threadIdx.x >> 6);   // 0..39
    int d = threadIdx.x & 63;
    float c = cs[t * 64 + d];
    float s = sn[t * 64 + d];
    size_t base = (head < NH)
        ? (size_t)t * QKV_N + head * HD
        : (size_t)t * QKV_N + K_OFF + (head - NH) * HD;
    float x1 = qkv[base + d];
    float x2 = qkv[base + 64 + d];
    qkv[base + d]      = x1 * c - x2 * s;
    qkv[base + 64 + d] = x2 * c + x1 * s;
}

// ============================================================================
// Flash attention; epilogue writes bf16 hi/lo directly (fused split)
// ============================================================================
#define ATT_SMEM_FLOATS (128*68 + 128*68 + 64*128 + 64*68)

__global__ void __launch_bounds__(256) attn_kernel(
    const float* __restrict__ qkv,
    __nv_bfloat16* __restrict__ ohi, __nv_bfloat16* __restrict__ olo)
{
    extern __shared__ float sm[];
    float* Qs = sm;                 // [128][68]
    float* Ks = Qs + 128 * 68;      // [128][68]
    float* Vs = Ks + 128 * 68;      // [64][128]
    float* Ss = Vs + 64 * 128;      // [64][68]

    const int tid = threadIdx.x;
    const int h   = blockIdx.y;
    const int qb  = blockIdx.x;

    int seq, qb_local;
    if      (qb < 8)  { seq = 0; qb_local = qb; }
    else if (qb < 20) { seq = 1; qb_local = qb - 8; }
    else if (qb < 26) { seq = 2; qb_local = qb - 20; }
    else              { seq = 3; qb_local = qb - 26; }
    const int cu[4] = {0, 512, 1280, 1664};
    const int seq_start = cu[seq];
    const int q_start = seq_start + qb_local * 64;
    const int kh = h >> 2;

    const int ty = tid >> 4, tx = tid & 15;
    const int row = tid >> 2, q = tid & 3;

    {
        size_t qbase = (size_t)q_start * QKV_N + (size_t)h * HD;
#pragma unroll
        for (int i = 0; i < 8; i++) {
            int id = tid + i * 256;
            int rr = id >> 5;
            int d4 = (id & 31) << 2;
            float4 v = *(const float4*)(qkv + qbase + (size_t)rr * QKV_N + d4);
            Qs[(d4 + 0) * 68 + rr] = v.x;
            Qs[(d4 + 1) * 68 + rr] = v.y;
            Qs[(d4 + 2) * 68 + rr] = v.z;
            Qs[(d4 + 3) * 68 + rr] = v.w;
        }
    }

    float m_run = -INFINITY;
    float l_run = 0.0f;
    float4 o[8];
#pragma unroll
    for (int i = 0; i < 8; i++) o[i] = make_float4(0.f, 0.f, 0.f, 0.f);

    __syncthreads();

    for (int kb = 0; kb <= qb_local; kb++) {
        size_t kbase = (size_t)(seq_start + kb * 64) * QKV_N + K_OFF + (size_t)kh * HD;
        size_t vbase = (size_t)(seq_start + kb * 64) * QKV_N + V_OFF + (size_t)kh * HD;
#pragma unroll
        for (int i = 0; i < 8; i++) {
            int id = tid + i * 256;
            int rr = id >> 5;
            int d4 = (id & 31) << 2;
            float4 kv = *(const float4*)(qkv + kbase + (size_t)rr * QKV_N + d4);
            Ks[(d4 + 0) * 68 + rr] = kv.x;
            Ks[(d4 + 1) * 68 + rr] = kv.y;
            Ks[(d4 + 2) * 68 + rr] = kv.z;
            Ks[(d4 + 3) * 68 + rr] = kv.w;
            float4 vv = *(const float4*)(qkv + vbase + (size_t)rr * QKV_N + d4);
            *(float4*)&Vs[rr * 128 + d4] = vv;
        }
        __syncthreads();

        float s[4][4];
#pragma unroll
        for (int i = 0; i < 4; i++)
#pragma unroll
            for (int j = 0; j < 4; j++) s[i][j] = 0.0f;

#pragma unroll 4
        for (int k = 0; k < 128; k++) {
            float4 qv = *(const float4*)&Qs[k * 68 + ty * 4];
            float4 kv = *(const float4*)&Ks[k * 68 + tx * 4];
            float qa[4] = {qv.x, qv.y, qv.z, qv.w};
            float ka[4] = {kv.x, kv.y, kv.z, kv.w};
#pragma unroll
            for (int i = 0; i < 4; i++)
#pragma unroll
                for (int j = 0; j < 4; j++)
                    s[i][j] = fmaf(qa[i], ka[j], s[i][j]);
        }

        bool diag = (kb == qb_local);
#pragma unroll
        for (int i = 0; i < 4; i++) {
            int rr = ty * 4 + i;
            float4 v;
            float vs[4];
#pragma unroll
            for (int j = 0; j < 4; j++) {
                float val = s[i][j] * SCALE;
                if (diag && (tx * 4 + j > rr)) val = -1e30f;
                vs[j] = val;
            }
            v.x = vs[0]; v.y = vs[1]; v.z = vs[2]; v.w = vs[3];
            *(float4*)&Ss[rr * 68 + tx * 4] = v;
        }
        __syncthreads();

        float lmax = -INFINITY;
#pragma unroll
        for (int jj = 0; jj < 16; jj++)
            lmax = fmaxf(lmax, Ss[row * 68 + q * 16 + jj]);
        lmax = fmaxf(lmax, __shfl_xor_sync(0xffffffffu, lmax, 1));
        lmax = fmaxf(lmax, __shfl_xor_sync(0xffffffffu, lmax, 2));
        float m_new = fmaxf(m_run, lmax);
        float alpha = __expf(m_run - m_new);

        float lsum = 0.0f;
#pragma unroll
        for (int jj = 0; jj < 16; jj++) {
            float p = __expf(Ss[row * 68 + q * 16 + jj] - m_new);
            Ss[row * 68 + q * 16 + jj] = p;
            lsum += p;
        }
        lsum += __shfl_xor_sync(0xffffffffu, lsum, 1);
        lsum += __shfl_xor_sync(0xffffffffu, lsum, 2);
        l_run = l_run * alpha + lsum;
        m_run = m_new;
        __syncthreads();

#pragma unroll
        for (int i = 0; i < 8; i++) {
            o[i].x *= alpha; o[i].y *= alpha; o[i].z *= alpha; o[i].w *= alpha;
        }
#pragma unroll 2
        for (int j = 0; j < 64; j++) {
            float p = Ss[row * 68 + j];
#pragma unroll
            for (int i = 0; i < 8; i++) {
                float4 vv = *(const float4*)&Vs[j * 128 + q * 4 + 16 * i];
                o[i].x = fmaf(p, vv.x, o[i].x);
                o[i].y = fmaf(p, vv.y, o[i].y);
                o[i].z = fmaf(p, vv.z, o[i].z);
                o[i].w = fmaf(p, vv.w, o[i].w);
            }
        }
        __syncthreads();
    }

    // ---- normalize and write bf16 hi/lo (fused split for O-projection) ----
    float inv = 1.0f / l_run;
    size_t obase = (size_t)(q_start + row) * DM + (size_t)h * HD;
#pragma unroll
    for (int i = 0; i < 8; i++) {
        float a[4] = {o[i].x * inv, o[i].y * inv, o[i].z * inv, o[i].w * inv};
        __nv_bfloat16 hh[4], ll[4];
#pragma unroll
        for (int j = 0; j < 4; j++) {
            hh[j] = __float2bfloat16(a[j]);
            ll[j] = __float2bfloat16(a[j] - __bfloat162float(hh[j]));
        }
        *(uint2*)(ohi + obase + q * 4 + 16 * i) = *(uint2*)hh;
        *(uint2*)(olo + obase + q * 4 + 16 * i) = *(uint2*)ll;
    }
}

// ============================================================================
// launch
// ============================================================================
extern "C" void kernel_launch(void* const* d_in, const int* in_sizes, int n_in,
                              void* d_out, int out_size)
{
    const float* hs    = (const float*)d_in[0];
    const float* w_qkv = (const float*)d_in[1];
    const float* w_o   = (const float*)d_in[2];
    const float* cs    = (const float*)d_in[3];
    const float* sn    = (const float*)d_in[4];
    (void)in_sizes; (void)n_in;

    float* qkv_buf = nullptr;
    __nv_bfloat16 *ahi, *alo, *bhi, *blo;
    cudaGetSymbolAddress((void**)&qkv_buf, g_qkv);
    cudaGetSymbolAddress((void**)&ahi, g_ahi);
    cudaGetSymbolAddress((void**)&alo, g_alo);
    cudaGetSymbolAddress((void**)&bhi, g_bhi);
    cudaGetSymbolAddress((void**)&blo, g_blo);

    static int attr_set = 0;
    if (!attr_set) {
        cudaFuncSetAttribute(attn_kernel, cudaFuncAttributeMaxDynamicSharedMemorySize,
                             (int)(ATT_SMEM_FLOATS * sizeof(float)));
        cudaFuncSetAttribute(gemm_tc_kernel, cudaFuncAttributeMaxDynamicSharedMemorySize,
                             GEMM_SMEM);
        attr_set = 1;
    }

    // split inputs to bf16 hi/lo
    split_kernel<<<(T_TOK * DM / 4) / 256, 256>>>(hs, ahi, alo, T_TOK * DM / 4);
    split_kernel<<<(QKV_N * DM / 4) / 256, 256>>>(w_qkv, bhi, blo, QKV_N * DM / 4);

    // QKV projection + clip (tensor cores)
    gemm_tc_kernel<<<dim3(QKV_N / 128, T_TOK / 128), 256, GEMM_SMEM>>>(
        ahi, alo, bhi, blo, qkv_buf, QKV_N, 1);

    // RoPE on Q and K
    rope_kernel<<<dim3(T_TOK, 10), 256>>>(qkv_buf, cs, sn);

    // attention (writes bf16 hi/lo of output directly)
    attn_kernel<<<dim3(32, NH), 256, ATT_SMEM_FLOATS * sizeof(float)>>>(qkv_buf, ahi, alo);

    // split w_o, then output projection
    split_kernel<<<(DM * DM / 4) / 256, 256>>>(w_o, bhi, blo, DM * DM / 4);

    gemm_tc_kernel<<<dim3(DM / 128, T_TOK / 128), 256, GEMM_SMEM>>>(
        ahi, alo, bhi, blo, (float*)d_out, DM, 0);
}

// round 5
// speedup vs baseline: 2.8154x; 1.2177x over previous
#include <cuda_runtime.h>
#include <cuda_fp16.h>
#include <math.h>
#include <cstdint>

// ---------------- problem constants (fixed by setup_inputs) ----------------
#define T_TOK   2048
#define DM      4096
#define NH      32
#define KVH     8
#define HD      128
#define QKV_N   6144          // 4096 + 2*8*128
#define K_OFF   4096
#define V_OFF   5120
#define CLIPV   8.0f
#define SCALE   0.08838834764831845f   // 1/sqrt(128)
#define KTOT    4096

// ---------------- scratch ----------------
__device__ float g_qkv[T_TOK * QKV_N];
__device__ __align__(16) __half g_ah [T_TOK * DM];     // A (fp16, rounded)
__device__ __align__(16) __half g_bhi[QKV_N * DM];     // B hi
__device__ __align__(16) __half g_blo[QKV_N * DM];     // B lo

// ============================ PTX helpers ============================
__device__ __forceinline__ uint32_t smem_u32_of(const void* p) {
    uint32_t a;
    asm("{ .reg .u64 t; cvta.to.shared.u64 t, %1; cvt.u32.u64 %0, t; }"
        : "=r"(a) : "l"(p));
    return a;
}
__device__ __forceinline__ void cp_async16(uint32_t dst, const void* src) {
    asm volatile("cp.async.cg.shared.global [%0], [%1], 16;" :: "r"(dst), "l"(src));
}
__device__ __forceinline__ void cp_commit() {
    asm volatile("cp.async.commit_group;" ::: "memory");
}
template<int N> __device__ __forceinline__ void cp_wait() {
    asm volatile("cp.async.wait_group %0;" :: "n"(N) : "memory");
}
__device__ __forceinline__ void ldsm4(uint32_t (&r)[4], uint32_t addr) {
    asm volatile("ldmatrix.sync.aligned.m8n8.x4.shared.b16 {%0,%1,%2,%3}, [%4];"
        : "=r"(r[0]), "=r"(r[1]), "=r"(r[2]), "=r"(r[3]) : "r"(addr));
}
__device__ __forceinline__ void mma16816(float (&d)[4], const uint32_t (&a)[4],
                                         const uint32_t* b) {
    asm volatile("mma.sync.aligned.m16n8k16.row.col.f32.f16.f16.f32 "
        "{%0,%1,%2,%3}, {%4,%5,%6,%7}, {%8,%9}, {%0,%1,%2,%3};"
        : "+f"(d[0]), "+f"(d[1]), "+f"(d[2]), "+f"(d[3])
        : "r"(a[0]), "r"(a[1]), "r"(a[2]), "r"(a[3]), "r"(b[0]), "r"(b[1]));
}

// ============================================================================
// convert fp32 -> fp16 (A side)
// ============================================================================
__global__ void __launch_bounds__(256) cvt_half_kernel(
    const float* __restrict__ in, __half* __restrict__ out, int n4)
{
    int i = blockIdx.x * 256 + threadIdx.x;
    if (i >= n4) return;
    float4 v = ((const float4*)in)[i];
    __half h[4] = {__float2half(v.x), __float2half(v.y),
                   __float2half(v.z), __float2half(v.w)};
    ((uint2*)out)[i] = *(uint2*)h;
}

// ============================================================================
// split fp32 -> fp16 hi/lo (B side)
// ============================================================================
__global__ void __launch_bounds__(256) split_kernel(
    const float* __restrict__ in, __half* __restrict__ hi,
    __half* __restrict__ lo, int n4)
{
    int i = blockIdx.x * 256 + threadIdx.x;
    if (i >= n4) return;
    float4 v = ((const float4*)in)[i];
    float a[4] = {v.x, v.y, v.z, v.w};
    __half h[4], l[4];
#pragma unroll
    for (int j = 0; j < 4; j++) {
        h[j] = __float2half(a[j]);
        l[j] = __float2half(a[j] - __half2float(h[j]));
    }
    ((uint2*)hi)[i] = *(uint2*)h;
    ((uint2*)lo)[i] = *(uint2*)l;
}

// ============================================================================
// HMMA GEMM: C[M,N] = A[M,K] * B[N,K]^T, fp16 2-pass (A16*Bhi + A16*Blo).
// CTA 128x128, BK=64, 8 warps (2x4), warp tile 64x32 (4x4 m16n8k16 atoms).
// Smem per stage: A|Bhi|Blo, each [128 rows][64 fp16] (128B rows,
// 16B chunks XOR-swizzled). 3 stages = 144KB. One barrier per chunk.
// ============================================================================
#define STAGE_BYTES 49152
#define NSTAGE      3
#define GEMM_SMEM   (NSTAGE * STAGE_BYTES)
#define NCHUNK      (KTOT / 64)

__global__ void __launch_bounds__(256, 1) gemm_tc_kernel(
    const __half* __restrict__ Ah, const __half* __restrict__ Bhi,
    const __half* __restrict__ Blo,
    float* __restrict__ C, int Ntot, int doClip)
{
    extern __shared__ char smem[];
    const uint32_t sb = smem_u32_of(smem);
    const int tid  = threadIdx.x;
    const int wid  = tid >> 5;
    const int lane = tid & 31;
    const int warp_m = wid >> 2;      // 0..1
    const int warp_n = wid & 3;       // 0..3
    const int m0 = blockIdx.y * 128;
    const int n0 = blockIdx.x * 128;

    const __half* srcs[3];
    srcs[0] = Ah; srcs[1] = Bhi; srcs[2] = Blo;

    // ldmatrix per-lane geometry
    const int g = lane >> 3, r = lane & 7;
    const int a_row  = warp_m * 64 + (g & 1) * 8 + r;   // + mi*16
    const int a_csel = g >> 1;
    const int b_row  = warp_n * 32 + (g >> 1) * 8 + r;  // + j*16
    const int b_csel = g & 1;

    float acc[4][4][4];
#pragma unroll
    for (int i = 0; i < 4; i++)
#pragma unroll
        for (int j = 0; j < 4; j++)
#pragma unroll
            for (int k = 0; k < 4; k++) acc[i][j][k] = 0.0f;

#define LOAD_CHUNK(cc, ss) do { \
    const int k0_ = (cc) * 64; \
    const uint32_t sbase_ = sb + (ss) * STAGE_BYTES; \
    _Pragma("unroll") \
    for (int t_ = 0; t_ < 12; t_++) { \
        int id_ = tid + t_ * 256; \
        int tile_ = id_ >> 10; \
        int w_ = id_ & 1023; \
        int mrow_ = w_ >> 3; \
        int cch_ = w_ & 7; \
        int grow_ = (tile_ == 0) ? (m0 + mrow_) : (n0 + mrow_); \
        const void* src_ = srcs[tile_] + (size_t)grow_ * KTOT + k0_ + cch_ * 8; \
        uint32_t dst_ = sbase_ + tile_ * 16384 + mrow_ * 128 + ((cch_ ^ (mrow_ & 7)) << 4); \
        cp_async16(dst_, src_); \
    } \
    cp_commit(); \
} while (0)

    LOAD_CHUNK(0, 0);
    LOAD_CHUNK(1, 1);

    int stage = 0;      // c % 3
    int lstage = 2;     // (c+2) % 3
    for (int c = 0; c < NCHUNK; c++) {
        if (c == NCHUNK - 1) cp_wait<0>(); else cp_wait<1>();
        __syncthreads();

        if (c + 2 < NCHUNK) LOAD_CHUNK(c + 2, lstage);

        const uint32_t st = sb + stage * STAGE_BYTES;
#pragma unroll
        for (int s = 0; s < 4; s++) {
            uint32_t a_f[4][4];
#pragma unroll
            for (int mi = 0; mi < 4; mi++) {
                int m = a_row + mi * 16;
                uint32_t off = (uint32_t)(m * 128) +
                               ((((s << 1) + a_csel) ^ (m & 7)) << 4);
                ldsm4(a_f[mi], st + off);
            }
            uint32_t b_hi[2][4], b_lo[2][4];
#pragma unroll
            for (int j = 0; j < 2; j++) {
                int n = b_row + j * 16;
                uint32_t off = (uint32_t)(n * 128) +
                               ((((s << 1) + b_csel) ^ (n & 7)) << 4);
                ldsm4(b_hi[j], st + 16384 + off);
                ldsm4(b_lo[j], st + 32768 + off);
            }
#pragma unroll
            for (int mi = 0; mi < 4; mi++) {
#pragma unroll
                for (int nj = 0; nj < 4; nj++) {
                    const uint32_t* bh = &b_hi[nj >> 1][(nj & 1) * 2];
                    const uint32_t* bl = &b_lo[nj >> 1][(nj & 1) * 2];
                    mma16816(acc[mi][nj], a_f[mi], bh);
                    mma16816(acc[mi][nj], a_f[mi], bl);
                }
            }
        }
        stage = (stage == 2) ? 0 : stage + 1;
        lstage = (lstage == 2) ? 0 : lstage + 1;
    }

    // epilogue: direct float2 stores
    const int qrow = lane >> 2;
    const int qcol = (lane & 3) * 2;
#pragma unroll
    for (int mi = 0; mi < 4; mi++) {
#pragma unroll
        for (int nj = 0; nj < 4; nj++) {
            int m = m0 + warp_m * 64 + mi * 16 + qrow;
            int n = n0 + warp_n * 32 + nj * 8 + qcol;
            float v0 = acc[mi][nj][0], v1 = acc[mi][nj][1];
            float v2 = acc[mi][nj][2], v3 = acc[mi][nj][3];
            if (doClip) {
                v0 = fminf(CLIPV, fmaxf(-CLIPV, v0));
                v1 = fminf(CLIPV, fmaxf(-CLIPV, v1));
                v2 = fminf(CLIPV, fmaxf(-CLIPV, v2));
                v3 = fminf(CLIPV, fmaxf(-CLIPV, v3));
            }
            float2 p0 = make_float2(v0, v1);
            float2 p1 = make_float2(v2, v3);
            *(float2*)(C + (size_t)m * Ntot + n) = p0;
            *(float2*)(C + (size_t)(m + 8) * Ntot + n) = p1;
        }
    }
}

// ============================================================================
// RoPE in-place on g_qkv: heads 0..31 = Q, 32..39 = K
// ============================================================================
__global__ void __launch_bounds__(256) rope_kernel(
    float* __restrict__ qkv, const float* __restrict__ cs, const float* __restrict__ sn)
{
    int t = blockIdx.x;
    int head = blockIdx.y * 4 + (threadIdx.x >> 6);   // 0..39
    int d = threadIdx.x & 63;
    float c = cs[t * 64 + d];
    float s = sn[t * 64 + d];
    size_t base = (head < NH)
        ? (size_t)t * QKV_N + head * HD
        : (size_t)t * QKV_N + K_OFF + (head - NH) * HD;
    float x1 = qkv[base + d];
    float x2 = qkv[base + 64 + d];
    qkv[base + d]      = x1 * c - x2 * s;
    qkv[base + 64 + d] = x2 * c + x1 * s;
}

// ============================================================================
// Flash attention; epilogue writes fp16 directly (A of O-projection)
// ============================================================================
#define ATT_SMEM_FLOATS (128*68 + 128*68 + 64*128 + 64*68)

__global__ void __launch_bounds__(256) attn_kernel(
    const float* __restrict__ qkv, __half* __restrict__ oh)
{
    extern __shared__ float sm[];
    float* Qs = sm;                 // [128][68]
    float* Ks = Qs + 128 * 68;      // [128][68]
    float* Vs = Ks + 128 * 68;      // [64][128]
    float* Ss = Vs + 64 * 128;      // [64][68]

    const int tid = threadIdx.x;
    const int h   = blockIdx.y;
    const int qb  = blockIdx.x;

    int seq, qb_local;
    if      (qb < 8)  { seq = 0; qb_local = qb; }
    else if (qb < 20) { seq = 1; qb_local = qb - 8; }
    else if (qb < 26) { seq = 2; qb_local = qb - 20; }
    else              { seq = 3; qb_local = qb - 26; }
    const int cu[4] = {0, 512, 1280, 1664};
    const int seq_start = cu[seq];
    const int q_start = seq_start + qb_local * 64;
    const int kh = h >> 2;

    const int ty = tid >> 4, tx = tid & 15;
    const int row = tid >> 2, q = tid & 3;

    {
        size_t qbase = (size_t)q_start * QKV_N + (size_t)h * HD;
#pragma unroll
        for (int i = 0; i < 8; i++) {
            int id = tid + i * 256;
            int rr = id >> 5;
            int d4 = (id & 31) << 2;
            float4 v = *(const float4*)(qkv + qbase + (size_t)rr * QKV_N + d4);
            Qs[(d4 + 0) * 68 + rr] = v.x;
            Qs[(d4 + 1) * 68 + rr] = v.y;
            Qs[(d4 + 2) * 68 + rr] = v.z;
            Qs[(d4 + 3) * 68 + rr] = v.w;
        }
    }

    float m_run = -INFINITY;
    float l_run = 0.0f;
    float4 o[8];
#pragma unroll
    for (int i = 0; i < 8; i++) o[i] = make_float4(0.f, 0.f, 0.f, 0.f);

    __syncthreads();

    for (int kb = 0; kb <= qb_local; kb++) {
        size_t kbase = (size_t)(seq_start + kb * 64) * QKV_N + K_OFF + (size_t)kh * HD;
        size_t vbase = (size_t)(seq_start + kb * 64) * QKV_N + V_OFF + (size_t)kh * HD;
#pragma unroll
        for (int i = 0; i < 8; i++) {
            int id = tid + i * 256;
            int rr = id >> 5;
            int d4 = (id & 31) << 2;
            float4 kv = *(const float4*)(qkv + kbase + (size_t)rr * QKV_N + d4);
            Ks[(d4 + 0) * 68 + rr] = kv.x;
            Ks[(d4 + 1) * 68 + rr] = kv.y;
            Ks[(d4 + 2) * 68 + rr] = kv.z;
            Ks[(d4 + 3) * 68 + rr] = kv.w;
            float4 vv = *(const float4*)(qkv + vbase + (size_t)rr * QKV_N + d4);
            *(float4*)&Vs[rr * 128 + d4] = vv;
        }
        __syncthreads();

        float s[4][4];
#pragma unroll
        for (int i = 0; i < 4; i++)
#pragma unroll
            for (int j = 0; j < 4; j++) s[i][j] = 0.0f;

#pragma unroll 4
        for (int k = 0; k < 128; k++) {
            float4 qv = *(const float4*)&Qs[k * 68 + ty * 4];
            float4 kv = *(const float4*)&Ks[k * 68 + tx * 4];
            float qa[4] = {qv.x, qv.y, qv.z, qv.w};
            float ka[4] = {kv.x, kv.y, kv.z, kv.w};
#pragma unroll
            for (int i = 0; i < 4; i++)
#pragma unroll
                for (int j = 0; j < 4; j++)
                    s[i][j] = fmaf(qa[i], ka[j], s[i][j]);
        }

        bool diag = (kb == qb_local);
#pragma unroll
        for (int i = 0; i < 4; i++) {
            int rr = ty * 4 + i;
            float4 v;
            float vs[4];
#pragma unroll
            for (int j = 0; j < 4; j++) {
                float val = s[i][j] * SCALE;
                if (diag && (tx * 4 + j > rr)) val = -1e30f;
                vs[j] = val;
            }
            v.x = vs[0]; v.y = vs[1]; v.z = vs[2]; v.w = vs[3];
            *(float4*)&Ss[rr * 68 + tx * 4] = v;
        }
        __syncthreads();

        float lmax = -INFINITY;
#pragma unroll
        for (int jj = 0; jj < 16; jj++)
            lmax = fmaxf(lmax, Ss[row * 68 + q * 16 + jj]);
        lmax = fmaxf(lmax, __shfl_xor_sync(0xffffffffu, lmax, 1));
        lmax = fmaxf(lmax, __shfl_xor_sync(0xffffffffu, lmax, 2));
        float m_new = fmaxf(m_run, lmax);
        float alpha = __expf(m_run - m_new);

        float lsum = 0.0f;
#pragma unroll
        for (int jj = 0; jj < 16; jj++) {
            float p = __expf(Ss[row * 68 + q * 16 + jj] - m_new);
            Ss[row * 68 + q * 16 + jj] = p;
            lsum += p;
        }
        lsum += __shfl_xor_sync(0xffffffffu, lsum, 1);
        lsum += __shfl_xor_sync(0xffffffffu, lsum, 2);
        l_run = l_run * alpha + lsum;
        m_run = m_new;
        __syncthreads();

#pragma unroll
        for (int i = 0; i < 8; i++) {
            o[i].x *= alpha; o[i].y *= alpha; o[i].z *= alpha; o[i].w *= alpha;
        }
#pragma unroll 2
        for (int j = 0; j < 64; j++) {
            float p = Ss[row * 68 + j];
#pragma unroll
            for (int i = 0; i < 8; i++) {
                float4 vv = *(const float4*)&Vs[j * 128 + q * 4 + 16 * i];
                o[i].x = fmaf(p, vv.x, o[i].x);
                o[i].y = fmaf(p, vv.y, o[i].y);
                o[i].z = fmaf(p, vv.z, o[i].z);
                o[i].w = fmaf(p, vv.w, o[i].w);
            }
        }
        __syncthreads();
    }

    // ---- normalize and write fp16 (A of O-projection) ----
    float inv = 1.0f / l_run;
    size_t obase = (size_t)(q_start + row) * DM + (size_t)h * HD;
#pragma unroll
    for (int i = 0; i < 8; i++) {
        __half hh[4] = {__float2half(o[i].x * inv), __float2half(o[i].y * inv),
                        __float2half(o[i].z * inv), __float2half(o[i].w * inv)};
        *(uint2*)(oh + obase + q * 4 + 16 * i) = *(uint2*)hh;
    }
}

// ============================================================================
// launch
// ============================================================================
extern "C" void kernel_launch(void* const* d_in, const int* in_sizes, int n_in,
                              void* d_out, int out_size)
{
    const float* hs    = (const float*)d_in[0];
    const float* w_qkv = (const float*)d_in[1];
    const float* w_o   = (const float*)d_in[2];
    const float* cs    = (const float*)d_in[3];
    const float* sn    = (const float*)d_in[4];
    (void)in_sizes; (void)n_in;

    float* qkv_buf = nullptr;
    __half *ah, *bhi, *blo;
    cudaGetSymbolAddress((void**)&qkv_buf, g_qkv);
    cudaGetSymbolAddress((void**)&ah, g_ah);
    cudaGetSymbolAddress((void**)&bhi, g_bhi);
    cudaGetSymbolAddress((void**)&blo, g_blo);

    static int attr_set = 0;
    if (!attr_set) {
        cudaFuncSetAttribute(attn_kernel, cudaFuncAttributeMaxDynamicSharedMemorySize,
                             (int)(ATT_SMEM_FLOATS * sizeof(float)));
        cudaFuncSetAttribute(gemm_tc_kernel, cudaFuncAttributeMaxDynamicSharedMemorySize,
                             GEMM_SMEM);
        attr_set = 1;
    }

    // convert A, split B
    cvt_half_kernel<<<(T_TOK * DM / 4) / 256, 256>>>(hs, ah, T_TOK * DM / 4);
    split_kernel<<<(QKV_N * DM / 4) / 256, 256>>>(w_qkv, bhi, blo, QKV_N * DM / 4);

    // QKV projection + clip (tensor cores)
    gemm_tc_kernel<<<dim3(QKV_N / 128, T_TOK / 128), 256, GEMM_SMEM>>>(
        ah, bhi, blo, qkv_buf, QKV_N, 1);

    // RoPE on Q and K
    rope_kernel<<<dim3(T_TOK, 10), 256>>>(qkv_buf, cs, sn);

    // attention (writes fp16 output directly)
    attn_kernel<<<dim3(32, NH), 256, ATT_SMEM_FLOATS * sizeof(float)>>>(qkv_buf, ah);

    // split w_o, then output projection
    split_kernel<<<(DM * DM / 4) / 256, 256>>>(w_o, bhi, blo, DM * DM / 4);

    gemm_tc_kernel<<<dim3(DM / 128, T_TOK / 128), 256, GEMM_SMEM>>>(
        ah, bhi, blo, (float*)d_out, DM, 0);
}

// round 6
// speedup vs baseline: 2.9036x; 1.0313x over previous
#include <cuda_runtime.h>
#include <cuda_fp16.h>
#include <math.h>
#include <cstdint>

// ---------------- problem constants (fixed by setup_inputs) ----------------
#define T_TOK   2048
#define DM      4096
#define NH      32
#define KVH     8
#define HD      128
#define QKV_N   6144          // 4096 + 2*8*128
#define K_OFF   4096
#define V_OFF   5120
#define CLIPV   8.0f
#define SCALE   0.08838834764831845f   // 1/sqrt(128)
#define KTOT    4096

// ---------------- scratch ----------------
__device__ float g_qkv[T_TOK * QKV_N];
__device__ __align__(16) __half g_ah [T_TOK * DM];     // A (fp16, rounded)
__device__ __align__(16) __half g_bhi[QKV_N * DM];     // B hi
__device__ __align__(16) __half g_blo[QKV_N * DM];     // B lo

// ============================ PTX helpers ============================
__device__ __forceinline__ uint32_t smem_u32_of(const void* p) {
    uint32_t a;
    asm("{ .reg .u64 t; cvta.to.shared.u64 t, %1; cvt.u32.u64 %0, t; }"
        : "=r"(a) : "l"(p));
    return a;
}
__device__ __forceinline__ void cp_async16(uint32_t dst, const void* src) {
    asm volatile("cp.async.cg.shared.global [%0], [%1], 16;" :: "r"(dst), "l"(src));
}
__device__ __forceinline__ void cp_commit() {
    asm volatile("cp.async.commit_group;" ::: "memory");
}
template<int N> __device__ __forceinline__ void cp_wait() {
    asm volatile("cp.async.wait_group %0;" :: "n"(N) : "memory");
}
__device__ __forceinline__ void ldsm4(uint32_t (&r)[4], uint32_t addr) {
    asm volatile("ldmatrix.sync.aligned.m8n8.x4.shared.b16 {%0,%1,%2,%3}, [%4];"
        : "=r"(r[0]), "=r"(r[1]), "=r"(r[2]), "=r"(r[3]) : "r"(addr));
}
__device__ __forceinline__ void mma16816(float (&d)[4], const uint32_t (&a)[4],
                                         const uint32_t* b) {
    asm volatile("mma.sync.aligned.m16n8k16.row.col.f32.f16.f16.f32 "
        "{%0,%1,%2,%3}, {%4,%5,%6,%7}, {%8,%9}, {%0,%1,%2,%3};"
        : "+f"(d[0]), "+f"(d[1]), "+f"(d[2]), "+f"(d[3])
        : "r"(a[0]), "r"(a[1]), "r"(a[2]), "r"(a[3]), "r"(b[0]), "r"(b[1]));
}

// ============================================================================
// convert fp32 -> fp16 (A side)
// ============================================================================
__global__ void __launch_bounds__(256) cvt_half_kernel(
    const float* __restrict__ in, __half* __restrict__ out, int n4)
{
    int i = blockIdx.x * 256 + threadIdx.x;
    if (i >= n4) return;
    float4 v = ((const float4*)in)[i];
    __half h[4] = {__float2half(v.x), __float2half(v.y),
                   __float2half(v.z), __float2half(v.w)};
    ((uint2*)out)[i] = *(uint2*)h;
}

// ============================================================================
// split fp32 -> fp16 hi/lo (B side)
// ============================================================================
__global__ void __launch_bounds__(256) split_kernel(
    const float* __restrict__ in, __half* __restrict__ hi,
    __half* __restrict__ lo, int n4)
{
    int i = blockIdx.x * 256 + threadIdx.x;
    if (i >= n4) return;
    float4 v = ((const float4*)in)[i];
    float a[4] = {v.x, v.y, v.z, v.w};
    __half h[4], l[4];
#pragma unroll
    for (int j = 0; j < 4; j++) {
        h[j] = __float2half(a[j]);
        l[j] = __float2half(a[j] - __half2float(h[j]));
    }
    ((uint2*)hi)[i] = *(uint2*)h;
    ((uint2*)lo)[i] = *(uint2*)l;
}

// ============================================================================
// HMMA GEMM: C[M,N] = A[M,K] * B[N,K]^T, fp16 2-pass (A16*Bhi + A16*Blo).
// CTA 128x128, BK=64, 8 warps (2x4), warp tile 64x32 (4x4 m16n8k16 atoms).
// Smem per stage: A|Bhi|Blo, each [128 rows][64 fp16], XOR-swizzled.
// 2 stages = 96KB -> 2 CTAs/SM. One barrier per chunk:
//   sync; load c+1 into stage freed by c-1; wait chunk c; compute c.
// ============================================================================
#define STAGE_BYTES 49152
#define NSTAGE      2
#define GEMM_SMEM   (NSTAGE * STAGE_BYTES)
#define NCHUNK      (KTOT / 64)

__global__ void __launch_bounds__(256, 2) gemm_tc_kernel(
    const __half* __restrict__ Ah, const __half* __restrict__ Bhi,
    const __half* __restrict__ Blo,
    float* __restrict__ C, int Ntot, int doClip)
{
    extern __shared__ char smem[];
    const uint32_t sb = smem_u32_of(smem);
    const int tid  = threadIdx.x;
    const int wid  = tid >> 5;
    const int lane = tid & 31;
    const int warp_m = wid >> 2;      // 0..1
    const int warp_n = wid & 3;       // 0..3
    const int m0 = blockIdx.y * 128;
    const int n0 = blockIdx.x * 128;

    const __half* srcs[3];
    srcs[0] = Ah; srcs[1] = Bhi; srcs[2] = Blo;

    // ldmatrix per-lane geometry
    const int g = lane >> 3, r = lane & 7;
    const int a_row  = warp_m * 64 + (g & 1) * 8 + r;   // + mi*16
    const int a_csel = g >> 1;
    const int b_row  = warp_n * 32 + (g >> 1) * 8 + r;  // + j*16
    const int b_csel = g & 1;

    float acc[4][4][4];
#pragma unroll
    for (int i = 0; i < 4; i++)
#pragma unroll
        for (int j = 0; j < 4; j++)
#pragma unroll
            for (int k = 0; k < 4; k++) acc[i][j][k] = 0.0f;

#define LOAD_CHUNK(cc, ss) do { \
    const int k0_ = (cc) * 64; \
    const uint32_t sbase_ = sb + (ss) * STAGE_BYTES; \
    _Pragma("unroll") \
    for (int t_ = 0; t_ < 12; t_++) { \
        int id_ = tid + t_ * 256; \
        int tile_ = id_ >> 10; \
        int w_ = id_ & 1023; \
        int mrow_ = w_ >> 3; \
        int cch_ = w_ & 7; \
        int grow_ = (tile_ == 0) ? (m0 + mrow_) : (n0 + mrow_); \
        const void* src_ = srcs[tile_] + (size_t)grow_ * KTOT + k0_ + cch_ * 8; \
        uint32_t dst_ = sbase_ + tile_ * 16384 + mrow_ * 128 + ((cch_ ^ (mrow_ & 7)) << 4); \
        cp_async16(dst_, src_); \
    } \
    cp_commit(); \
} while (0)

    LOAD_CHUNK(0, 0);

    for (int c = 0; c < NCHUNK; c++) {
        __syncthreads();   // all warps done computing c-1; stage (c-1)&1 free

        if (c + 1 < NCHUNK) {
            LOAD_CHUNK(c + 1, (c + 1) & 1);
            cp_wait<1>();          // chunk c landed; c+1 still in flight
        } else {
            cp_wait<0>();
        }
        __syncthreads();   // chunk c visible to all warps

        const uint32_t st = sb + (c & 1) * STAGE_BYTES;
#pragma unroll
        for (int s = 0; s < 4; s++) {
            uint32_t a_f[4][4];
#pragma unroll
            for (int mi = 0; mi < 4; mi++) {
                int m = a_row + mi * 16;
                uint32_t off = (uint32_t)(m * 128) +
                               ((((s << 1) + a_csel) ^ (m & 7)) << 4);
                ldsm4(a_f[mi], st + off);
            }
            uint32_t b_hi[2][4], b_lo[2][4];
#pragma unroll
            for (int j = 0; j < 2; j++) {
                int n = b_row + j * 16;
                uint32_t off = (uint32_t)(n * 128) +
                               ((((s << 1) + b_csel) ^ (n & 7)) << 4);
                ldsm4(b_hi[j], st + 16384 + off);
                ldsm4(b_lo[j], st + 32768 + off);
            }
#pragma unroll
            for (int mi = 0; mi < 4; mi++) {
#pragma unroll
                for (int nj = 0; nj < 4; nj++) {
                    const uint32_t* bh = &b_hi[nj >> 1][(nj & 1) * 2];
                    const uint32_t* bl = &b_lo[nj >> 1][(nj & 1) * 2];
                    mma16816(acc[mi][nj], a_f[mi], bh);
                    mma16816(acc[mi][nj], a_f[mi], bl);
                }
            }
        }
    }

    // epilogue: direct float2 stores
    const int qrow = lane >> 2;
    const int qcol = (lane & 3) * 2;
#pragma unroll
    for (int mi = 0; mi < 4; mi++) {
#pragma unroll
        for (int nj = 0; nj < 4; nj++) {
            int m = m0 + warp_m * 64 + mi * 16 + qrow;
            int n = n0 + warp_n * 32 + nj * 8 + qcol;
            float v0 = acc[mi][nj][0], v1 = acc[mi][nj][1];
            float v2 = acc[mi][nj][2], v3 = acc[mi][nj][3];
            if (doClip) {
                v0 = fminf(CLIPV, fmaxf(-CLIPV, v0));
                v1 = fminf(CLIPV, fmaxf(-CLIPV, v1));
                v2 = fminf(CLIPV, fmaxf(-CLIPV, v2));
                v3 = fminf(CLIPV, fmaxf(-CLIPV, v3));
            }
            float2 p0 = make_float2(v0, v1);
            float2 p1 = make_float2(v2, v3);
            *(float2*)(C + (size_t)m * Ntot + n) = p0;
            *(float2*)(C + (size_t)(m + 8) * Ntot + n) = p1;
        }
    }
}

// ============================================================================
// RoPE in-place on g_qkv: heads 0..31 = Q, 32..39 = K
// ============================================================================
__global__ void __launch_bounds__(256) rope_kernel(
    float* __restrict__ qkv, const float* __restrict__ cs, const float* __restrict__ sn)
{
    int t = blockIdx.x;
    int head = blockIdx.y * 4 + (threadIdx.x >> 6);   // 0..39
    int d = threadIdx.x & 63;
    float c = cs[t * 64 + d];
    float s = sn[t * 64 + d];
    size_t base = (head < NH)
        ? (size_t)t * QKV_N + head * HD
        : (size_t)t * QKV_N + K_OFF + (head - NH) * HD;
    float x1 = qkv[base + d];
    float x2 = qkv[base + 64 + d];
    qkv[base + d]      = x1 * c - x2 * s;
    qkv[base + 64 + d] = x2 * c + x1 * s;
}

// ============================================================================
// Flash attention; epilogue writes fp16 directly (A of O-projection)
// ============================================================================
#define ATT_SMEM_FLOATS (128*68 + 128*68 + 64*128 + 64*68)

__global__ void __launch_bounds__(256) attn_kernel(
    const float* __restrict__ qkv, __half* __restrict__ oh)
{
    extern __shared__ float sm[];
    float* Qs = sm;                 // [128][68]
    float* Ks = Qs + 128 * 68;      // [128][68]
    float* Vs = Ks + 128 * 68;      // [64][128]
    float* Ss = Vs + 64 * 128;      // [64][68]

    const int tid = threadIdx.x;
    const int h   = blockIdx.y;
    const int qb  = blockIdx.x;

    int seq, qb_local;
    if      (qb < 8)  { seq = 0; qb_local = qb; }
    else if (qb < 20) { seq = 1; qb_local = qb - 8; }
    else if (qb < 26) { seq = 2; qb_local = qb - 20; }
    else              { seq = 3; qb_local = qb - 26; }
    const int cu[4] = {0, 512, 1280, 1664};
    const int seq_start = cu[seq];
    const int q_start = seq_start + qb_local * 64;
    const int kh = h >> 2;

    const int ty = tid >> 4, tx = tid & 15;
    const int row = tid >> 2, q = tid & 3;

    {
        size_t qbase = (size_t)q_start * QKV_N + (size_t)h * HD;
#pragma unroll
        for (int i = 0; i < 8; i++) {
            int id = tid + i * 256;
            int rr = id >> 5;
            int d4 = (id & 31) << 2;
            float4 v = *(const float4*)(qkv + qbase + (size_t)rr * QKV_N + d4);
            Qs[(d4 + 0) * 68 + rr] = v.x;
            Qs[(d4 + 1) * 68 + rr] = v.y;
            Qs[(d4 + 2) * 68 + rr] = v.z;
            Qs[(d4 + 3) * 68 + rr] = v.w;
        }
    }

    float m_run = -INFINITY;
    float l_run = 0.0f;
    float4 o[8];
#pragma unroll
    for (int i = 0; i < 8; i++) o[i] = make_float4(0.f, 0.f, 0.f, 0.f);

    __syncthreads();

    for (int kb = 0; kb <= qb_local; kb++) {
        size_t kbase = (size_t)(seq_start + kb * 64) * QKV_N + K_OFF + (size_t)kh * HD;
        size_t vbase = (size_t)(seq_start + kb * 64) * QKV_N + V_OFF + (size_t)kh * HD;
#pragma unroll
        for (int i = 0; i < 8; i++) {
            int id = tid + i * 256;
            int rr = id >> 5;
            int d4 = (id & 31) << 2;
            float4 kv = *(const float4*)(qkv + kbase + (size_t)rr * QKV_N + d4);
            Ks[(d4 + 0) * 68 + rr] = kv.x;
            Ks[(d4 + 1) * 68 + rr] = kv.y;
            Ks[(d4 + 2) * 68 + rr] = kv.z;
            Ks[(d4 + 3) * 68 + rr] = kv.w;
            float4 vv = *(const float4*)(qkv + vbase + (size_t)rr * QKV_N + d4);
            *(float4*)&Vs[rr * 128 + d4] = vv;
        }
        __syncthreads();

        float s[4][4];
#pragma unroll
        for (int i = 0; i < 4; i++)
#pragma unroll
            for (int j = 0; j < 4; j++) s[i][j] = 0.0f;

#pragma unroll 4
        for (int k = 0; k < 128; k++) {
            float4 qv = *(const float4*)&Qs[k * 68 + ty * 4];
            float4 kv = *(const float4*)&Ks[k * 68 + tx * 4];
            float qa[4] = {qv.x, qv.y, qv.z, qv.w};
            float ka[4] = {kv.x, kv.y, kv.z, kv.w};
#pragma unroll
            for (int i = 0; i < 4; i++)
#pragma unroll
                for (int j = 0; j < 4; j++)
                    s[i][j] = fmaf(qa[i], ka[j], s[i][j]);
        }

        bool diag = (kb == qb_local);
#pragma unroll
        for (int i = 0; i < 4; i++) {
            int rr = ty * 4 + i;
            float4 v;
            float vs[4];
#pragma unroll
            for (int j = 0; j < 4; j++) {
                float val = s[i][j] * SCALE;
                if (diag && (tx * 4 + j > rr)) val = -1e30f;
                vs[j] = val;
            }
            v.x = vs[0]; v.y = vs[1]; v.z = vs[2]; v.w = vs[3];
            *(float4*)&Ss[rr * 68 + tx * 4] = v;
        }
        __syncthreads();

        float lmax = -INFINITY;
#pragma unroll
        for (int jj = 0; jj < 16; jj++)
            lmax = fmaxf(lmax, Ss[row * 68 + q * 16 + jj]);
        lmax = fmaxf(lmax, __shfl_xor_sync(0xffffffffu, lmax, 1));
        lmax = fmaxf(lmax, __shfl_xor_sync(0xffffffffu, lmax, 2));
        float m_new = fmaxf(m_run, lmax);
        float alpha = __expf(m_run - m_new);

        float lsum = 0.0f;
#pragma unroll
        for (int jj = 0; jj < 16; jj++) {
            float p = __expf(Ss[row * 68 + q * 16 + jj] - m_new);
            Ss[row * 68 + q * 16 + jj] = p;
            lsum += p;
        }
        lsum += __shfl_xor_sync(0xffffffffu, lsum, 1);
        lsum += __shfl_xor_sync(0xffffffffu, lsum, 2);
        l_run = l_run * alpha + lsum;
        m_run = m_new;
        __syncthreads();

#pragma unroll
        for (int i = 0; i < 8; i++) {
            o[i].x *= alpha; o[i].y *= alpha; o[i].z *= alpha; o[i].w *= alpha;
        }
#pragma unroll 2
        for (int j = 0; j < 64; j++) {
            float p = Ss[row * 68 + j];
#pragma unroll
            for (int i = 0; i < 8; i++) {
                float4 vv = *(const float4*)&Vs[j * 128 + q * 4 + 16 * i];
                o[i].x = fmaf(p, vv.x, o[i].x);
                o[i].y = fmaf(p, vv.y, o[i].y);
                o[i].z = fmaf(p, vv.z, o[i].z);
                o[i].w = fmaf(p, vv.w, o[i].w);
            }
        }
        __syncthreads();
    }

    // ---- normalize and write fp16 (A of O-projection) ----
    float inv = 1.0f / l_run;
    size_t obase = (size_t)(q_start + row) * DM + (size_t)h * HD;
#pragma unroll
    for (int i = 0; i < 8; i++) {
        __half hh[4] = {__float2half(o[i].x * inv), __float2half(o[i].y * inv),
                        __float2half(o[i].z * inv), __float2half(o[i].w * inv)};
        *(uint2*)(oh + obase + q * 4 + 16 * i) = *(uint2*)hh;
    }
}

// ============================================================================
// launch
// ============================================================================
extern "C" void kernel_launch(void* const* d_in, const int* in_sizes, int n_in,
                              void* d_out, int out_size)
{
    const float* hs    = (const float*)d_in[0];
    const float* w_qkv = (const float*)d_in[1];
    const float* w_o   = (const float*)d_in[2];
    const float* cs    = (const float*)d_in[3];
    const float* sn    = (const float*)d_in[4];
    (void)in_sizes; (void)n_in;

    float* qkv_buf = nullptr;
    __half *ah, *bhi, *blo;
    cudaGetSymbolAddress((void**)&qkv_buf, g_qkv);
    cudaGetSymbolAddress((void**)&ah, g_ah);
    cudaGetSymbolAddress((void**)&bhi, g_bhi);
    cudaGetSymbolAddress((void**)&blo, g_blo);

    static int attr_set = 0;
    if (!attr_set) {
        cudaFuncSetAttribute(attn_kernel, cudaFuncAttributeMaxDynamicSharedMemorySize,
                             (int)(ATT_SMEM_FLOATS * sizeof(float)));
        cudaFuncSetAttribute(gemm_tc_kernel, cudaFuncAttributeMaxDynamicSharedMemorySize,
                             GEMM_SMEM);
        attr_set = 1;
    }

    // convert A, split B
    cvt_half_kernel<<<(T_TOK * DM / 4) / 256, 256>>>(hs, ah, T_TOK * DM / 4);
    split_kernel<<<(QKV_N * DM / 4) / 256, 256>>>(w_qkv, bhi, blo, QKV_N * DM / 4);

    // QKV projection + clip (tensor cores)
    gemm_tc_kernel<<<dim3(QKV_N / 128, T_TOK / 128), 256, GEMM_SMEM>>>(
        ah, bhi, blo, qkv_buf, QKV_N, 1);

    // RoPE on Q and K
    rope_kernel<<<dim3(T_TOK, 10), 256>>>(qkv_buf, cs, sn);

    // attention (writes fp16 output directly)
    attn_kernel<<<dim3(32, NH), 256, ATT_SMEM_FLOATS * sizeof(float)>>>(qkv_buf, ah);

    // split w_o, then output projection
    split_kernel<<<(DM * DM / 4) / 256, 256>>>(w_o, bhi, blo, DM * DM / 4);

    gemm_tc_kernel<<<dim3(DM / 128, T_TOK / 128), 256, GEMM_SMEM>>>(
        ah, bhi, blo, (float*)d_out, DM, 0);
}

// round 7
// speedup vs baseline: 4.3754x; 1.5069x over previous
#include <cuda_runtime.h>
#include <cuda_fp16.h>
#include <math.h>
#include <cstdint>

// ---------------- problem constants ----------------
#define T_TOK   2048
#define DM      4096
#define NH      32
#define KVH     8
#define HD      128
#define QKV_N   6144
#define K_OFF   4096
#define V_OFF   5120
#define CLIPV   8.0f
#define SCALE   0.08838834764831845f
#define KTOT    4096

// ---------------- scratch ----------------
__device__ float g_qkv[T_TOK * QKV_N];
__device__ __align__(16) __half g_ah [T_TOK * DM];     // GEMM A (fp16)
__device__ __align__(16) __half g_bhi[QKV_N * DM];
__device__ __align__(16) __half g_blo[QKV_N * DM];
__device__ __align__(16) __half g_qhi[T_TOK * DM];
__device__ __align__(16) __half g_qlo[T_TOK * DM];
__device__ __align__(16) __half g_khi[T_TOK * KVH * HD];
__device__ __align__(16) __half g_klo[T_TOK * KVH * HD];
__device__ __align__(16) __half g_vthi[KVH * HD * T_TOK];   // [kvh][d][t]
__device__ __align__(16) __half g_vtlo[KVH * HD * T_TOK];

// ============================ PTX helpers ============================
__device__ __forceinline__ uint32_t smem_u32_of(const void* p) {
    uint32_t a;
    asm("{ .reg .u64 t; cvta.to.shared.u64 t, %1; cvt.u32.u64 %0, t; }"
        : "=r"(a) : "l"(p));
    return a;
}
__device__ __forceinline__ void cp_async16(uint32_t dst, const void* src) {
    asm volatile("cp.async.cg.shared.global [%0], [%1], 16;" :: "r"(dst), "l"(src));
}
__device__ __forceinline__ void cp_commit() {
    asm volatile("cp.async.commit_group;" ::: "memory");
}
template<int N> __device__ __forceinline__ void cp_wait() {
    asm volatile("cp.async.wait_group %0;" :: "n"(N) : "memory");
}
__device__ __forceinline__ void ldsm4(uint32_t (&r)[4], uint32_t addr) {
    asm volatile("ldmatrix.sync.aligned.m8n8.x4.shared.b16 {%0,%1,%2,%3}, [%4];"
        : "=r"(r[0]), "=r"(r[1]), "=r"(r[2]), "=r"(r[3]) : "r"(addr));
}
__device__ __forceinline__ void mma16816(float (&d)[4], const uint32_t (&a)[4],
                                         const uint32_t* b) {
    asm volatile("mma.sync.aligned.m16n8k16.row.col.f32.f16.f16.f32 "
        "{%0,%1,%2,%3}, {%4,%5,%6,%7}, {%8,%9}, {%0,%1,%2,%3};"
        : "+f"(d[0]), "+f"(d[1]), "+f"(d[2]), "+f"(d[3])
        : "r"(a[0]), "r"(a[1]), "r"(a[2]), "r"(a[3]), "r"(b[0]), "r"(b[1]));
}
__device__ __forceinline__ uint32_t swoff(int row, int cch) {
    return (uint32_t)(row * 128 + (((cch) ^ (row & 7)) << 4));
}

// ============================================================================
// convert fp32 -> fp16 (A side)
// ============================================================================
__global__ void __launch_bounds__(256) cvt_half_kernel(
    const float* __restrict__ in, __half* __restrict__ out, int n4)
{
    int i = blockIdx.x * 256 + threadIdx.x;
    if (i >= n4) return;
    float4 v = ((const float4*)in)[i];
    __half h[4] = {__float2half(v.x), __float2half(v.y),
                   __float2half(v.z), __float2half(v.w)};
    ((uint2*)out)[i] = *(uint2*)h;
}

// ============================================================================
// split fp32 -> fp16 hi/lo (B side)
// ============================================================================
__global__ void __launch_bounds__(256) split_kernel(
    const float* __restrict__ in, __half* __restrict__ hi,
    __half* __restrict__ lo, int n4)
{
    int i = blockIdx.x * 256 + threadIdx.x;
    if (i >= n4) return;
    float4 v = ((const float4*)in)[i];
    float a[4] = {v.x, v.y, v.z, v.w};
    __half h[4], l[4];
#pragma unroll
    for (int j = 0; j < 4; j++) {
        h[j] = __float2half(a[j]);
        l[j] = __float2half(a[j] - __half2float(h[j]));
    }
    ((uint2*)hi)[i] = *(uint2*)h;
    ((uint2*)lo)[i] = *(uint2*)l;
}

// ============================================================================
// HMMA GEMM (unchanged from R6 winner)
// ============================================================================
#define STAGE_BYTES 49152
#define NSTAGE      2
#define GEMM_SMEM   (NSTAGE * STAGE_BYTES)
#define NCHUNK      (KTOT / 64)

__global__ void __launch_bounds__(256, 2) gemm_tc_kernel(
    const __half* __restrict__ Ah, const __half* __restrict__ Bhi,
    const __half* __restrict__ Blo,
    float* __restrict__ C, int Ntot, int doClip)
{
    extern __shared__ char smem[];
    const uint32_t sb = smem_u32_of(smem);
    const int tid  = threadIdx.x;
    const int wid  = tid >> 5;
    const int lane = tid & 31;
    const int warp_m = wid >> 2;
    const int warp_n = wid & 3;
    const int m0 = blockIdx.y * 128;
    const int n0 = blockIdx.x * 128;

    const __half* srcs[3];
    srcs[0] = Ah; srcs[1] = Bhi; srcs[2] = Blo;

    const int g = lane >> 3, r = lane & 7;
    const int a_row  = warp_m * 64 + (g & 1) * 8 + r;
    const int a_csel = g >> 1;
    const int b_row  = warp_n * 32 + (g >> 1) * 8 + r;
    const int b_csel = g & 1;

    float acc[4][4][4];
#pragma unroll
    for (int i = 0; i < 4; i++)
#pragma unroll
        for (int j = 0; j < 4; j++)
#pragma unroll
            for (int k = 0; k < 4; k++) acc[i][j][k] = 0.0f;

#define LOAD_CHUNK(cc, ss) do { \
    const int k0_ = (cc) * 64; \
    const uint32_t sbase_ = sb + (ss) * STAGE_BYTES; \
    _Pragma("unroll") \
    for (int t_ = 0; t_ < 12; t_++) { \
        int id_ = tid + t_ * 256; \
        int tile_ = id_ >> 10; \
        int w_ = id_ & 1023; \
        int mrow_ = w_ >> 3; \
        int cch_ = w_ & 7; \
        int grow_ = (tile_ == 0) ? (m0 + mrow_) : (n0 + mrow_); \
        const void* src_ = srcs[tile_] + (size_t)grow_ * KTOT + k0_ + cch_ * 8; \
        uint32_t dst_ = sbase_ + tile_ * 16384 + mrow_ * 128 + ((cch_ ^ (mrow_ & 7)) << 4); \
        cp_async16(dst_, src_); \
    } \
    cp_commit(); \
} while (0)

    LOAD_CHUNK(0, 0);

    for (int c = 0; c < NCHUNK; c++) {
        __syncthreads();
        if (c + 1 < NCHUNK) {
            LOAD_CHUNK(c + 1, (c + 1) & 1);
            cp_wait<1>();
        } else {
            cp_wait<0>();
        }
        __syncthreads();

        const uint32_t st = sb + (c & 1) * STAGE_BYTES;
#pragma unroll
        for (int s = 0; s < 4; s++) {
            uint32_t a_f[4][4];
#pragma unroll
            for (int mi = 0; mi < 4; mi++) {
                int m = a_row + mi * 16;
                uint32_t off = (uint32_t)(m * 128) +
                               ((((s << 1) + a_csel) ^ (m & 7)) << 4);
                ldsm4(a_f[mi], st + off);
            }
            uint32_t b_hi[2][4], b_lo[2][4];
#pragma unroll
            for (int j = 0; j < 2; j++) {
                int n = b_row + j * 16;
                uint32_t off = (uint32_t)(n * 128) +
                               ((((s << 1) + b_csel) ^ (n & 7)) << 4);
                ldsm4(b_hi[j], st + 16384 + off);
                ldsm4(b_lo[j], st + 32768 + off);
            }
#pragma unroll
            for (int mi = 0; mi < 4; mi++) {
#pragma unroll
                for (int nj = 0; nj < 4; nj++) {
                    const uint32_t* bh = &b_hi[nj >> 1][(nj & 1) * 2];
                    const uint32_t* bl = &b_lo[nj >> 1][(nj & 1) * 2];
                    mma16816(acc[mi][nj], a_f[mi], bh);
                    mma16816(acc[mi][nj], a_f[mi], bl);
                }
            }
        }
    }

    const int qrow = lane >> 2;
    const int qcol = (lane & 3) * 2;
#pragma unroll
    for (int mi = 0; mi < 4; mi++) {
#pragma unroll
        for (int nj = 0; nj < 4; nj++) {
            int m = m0 + warp_m * 64 + mi * 16 + qrow;
            int n = n0 + warp_n * 32 + nj * 8 + qcol;
            float v0 = acc[mi][nj][0], v1 = acc[mi][nj][1];
            float v2 = acc[mi][nj][2], v3 = acc[mi][nj][3];
            if (doClip) {
                v0 = fminf(CLIPV, fmaxf(-CLIPV, v0));
                v1 = fminf(CLIPV, fmaxf(-CLIPV, v1));
                v2 = fminf(CLIPV, fmaxf(-CLIPV, v2));
                v3 = fminf(CLIPV, fmaxf(-CLIPV, v3));
            }
            *(float2*)(C + (size_t)m * Ntot + n) = make_float2(v0, v1);
            *(float2*)(C + (size_t)(m + 8) * Ntot + n) = make_float2(v2, v3);
        }
    }
}

// ============================================================================
// RoPE: read fp32 g_qkv, write fp16 hi/lo Q and K
// grid(T, 10), block 256: heads 0..31 Q, 32..39 K
// ============================================================================
__global__ void __launch_bounds__(256) rope_kernel(
    const float* __restrict__ qkv, const float* __restrict__ cs,
    const float* __restrict__ sn,
    __half* __restrict__ Qhi, __half* __restrict__ Qlo,
    __half* __restrict__ Khi, __half* __restrict__ Klo)
{
    int t = blockIdx.x;
    int head = blockIdx.y * 4 + (threadIdx.x >> 6);
    int d = threadIdx.x & 63;
    float c = cs[t * 64 + d];
    float s = sn[t * 64 + d];
    size_t base;
    size_t obase;
    __half *hi, *lo;
    if (head < NH) {
        base = (size_t)t * QKV_N + head * HD;
        obase = (size_t)t * DM + head * HD;
        hi = Qhi; lo = Qlo;
    } else {
        base = (size_t)t * QKV_N + K_OFF + (head - NH) * HD;
        obase = (size_t)t * (KVH * HD) + (head - NH) * HD;
        hi = Khi; lo = Klo;
    }
    float x1 = qkv[base + d];
    float x2 = qkv[base + 64 + d];
    float y1 = x1 * c - x2 * s;
    float y2 = x2 * c + x1 * s;
    __half h1 = __float2half(y1);
    __half h2 = __float2half(y2);
    hi[obase + d]      = h1;
    hi[obase + 64 + d] = h2;
    lo[obase + d]      = __float2half(y1 - __half2float(h1));
    lo[obase + 64 + d] = __float2half(y2 - __half2float(h2));
}

// ============================================================================
// V transpose: g_qkv V section -> Vt[kvh][d][t] fp16 hi/lo
// grid(T/64, KVH), block 256
// ============================================================================
__global__ void __launch_bounds__(256) vtrans_kernel(
    const float* __restrict__ qkv,
    __half* __restrict__ Vthi, __half* __restrict__ Vtlo)
{
    __shared__ float vt[64][133];
    const int tid = threadIdx.x;
    const int tok0 = blockIdx.x * 64;
    const int kvh = blockIdx.y;

    // load 64 x 128 fp32
#pragma unroll
    for (int i = 0; i < 8; i++) {
        int idx = tid + i * 256;         // float4 index, 2048 total
        int row = idx >> 5;
        int c4  = (idx & 31) << 2;
        float4 v = *(const float4*)(qkv + (size_t)(tok0 + row) * QKV_N + V_OFF
                                    + kvh * HD + c4);
        vt[row][c4] = v.x; vt[row][c4 + 1] = v.y;
        vt[row][c4 + 2] = v.z; vt[row][c4 + 3] = v.w;
    }
    __syncthreads();

    if (tid < 128) {
        int d = tid;
        size_t obase = ((size_t)kvh * HD + d) * T_TOK + tok0;
#pragma unroll
        for (int gb = 0; gb < 8; gb++) {
            __half hb[8], lb[8];
#pragma unroll
            for (int u = 0; u < 8; u++) {
                float v = vt[gb * 8 + u][d];
                hb[u] = __float2half(v);
                lb[u] = __float2half(v - __half2float(hb[u]));
            }
            *(uint4*)(Vthi + obase + gb * 8) = *(uint4*)hb;
            *(uint4*)(Vtlo + obase + gb * 8) = *(uint4*)lb;
        }
    }
}

// ============================================================================
// Tensor-core flash attention. BQ=BK=64, D=128, 8 warps.
// QK: 3-pass hi/lo (qh*kh + qh*kl + ql*kh), fp32 accum.
// PV: P fp16 x (Vhi + Vlo), fp32 accum.
// warp layout: warp_m = wid&3 (16 q rows), warp_n = wid>>2 (QK: 32 k cols;
// PV: 64 d cols = d-half select).
// ============================================================================
#define ATT_QHI 0
#define ATT_QLO 16384
#define ATT_KHI 32768
#define ATT_KLO 49152
#define ATT_VHI 65536
#define ATT_VLO 81920
#define ATT_PS  98304
#define ATT_SS  106496                 // float [64][68]
#define ATT_ALPHA (ATT_SS + 17408)
#define ATT_LROW  (ATT_ALPHA + 256)
#define ATT_SMEM  (ATT_LROW + 256)

__global__ void __launch_bounds__(256) attn_kernel(
    const __half* __restrict__ Qhi, const __half* __restrict__ Qlo,
    const __half* __restrict__ Khi, const __half* __restrict__ Klo,
    const __half* __restrict__ Vthi, const __half* __restrict__ Vtlo,
    __half* __restrict__ oh)
{
    extern __shared__ char smc[];
    const uint32_t sbm = smem_u32_of(smc);
    float* Ss     = (float*)(smc + ATT_SS);
    float* alphas = (float*)(smc + ATT_ALPHA);
    float* lrow   = (float*)(smc + ATT_LROW);

    const int tid = threadIdx.x;
    const int h   = blockIdx.y;
    const int qb  = blockIdx.x;

    int seq, qb_local;
    if      (qb < 8)  { seq = 0; qb_local = qb; }
    else if (qb < 20) { seq = 1; qb_local = qb - 8; }
    else if (qb < 26) { seq = 2; qb_local = qb - 20; }
    else              { seq = 3; qb_local = qb - 26; }
    const int cu[4] = {0, 512, 1280, 1664};
    const int seq_start = cu[seq];
    const int q_start = seq_start + qb_local * 64;
    const int kh = h >> 2;

    const int wid = tid >> 5, lane = tid & 31;
    const int warp_m = wid & 3;
    const int warp_n = wid >> 2;
    const int g = lane >> 3, r = lane & 7;
    const int a_row  = warp_m * 16 + (g & 1) * 8 + r;
    const int a_csel = g >> 1;
    const int b_row  = warp_n * 32 + (g >> 1) * 8 + r;
    const int b_csel = g & 1;
    const int pb_row = (g >> 1) * 8 + r;       // PV B rows (d local), + nb*16
    const int qrow = lane >> 2, qcol = (lane & 3) * 2;
    const int srow = tid >> 2, sq = tid & 3;   // softmax mapping

    // ---- load Q tiles (hi+lo) ----
#pragma unroll
    for (int t = 0; t < 8; t++) {
        int id = tid + t * 256;        // 0..2047
        int buf = id >> 10;            // 0 hi, 1 lo
        int w = id & 1023;
        int half_ = w >> 9;
        int w2 = w & 511;
        int trow = w2 >> 3, cch = w2 & 7;
        const __half* src = (buf ? Qlo : Qhi) +
            (size_t)(q_start + trow) * DM + h * HD + half_ * 64 + cch * 8;
        uint32_t dst = sbm + (buf ? ATT_QLO : ATT_QHI) + half_ * 8192 + swoff(trow, cch);
        cp_async16(dst, src);
    }

    float m_run = -INFINITY, l_run = 0.0f;
    float o[8][4];
#pragma unroll
    for (int i = 0; i < 8; i++)
#pragma unroll
        for (int j = 0; j < 4; j++) o[i][j] = 0.0f;

    for (int kb = 0; kb <= qb_local; kb++) {
        const int tok0 = seq_start + kb * 64;
        // ---- load K (hi/lo) and Vt (hi/lo) tiles ----
#pragma unroll
        for (int t = 0; t < 8; t++) {
            int id = tid + t * 256;
            int buf = id >> 10;
            int w = id & 1023;
            int half_ = w >> 9;
            int w2 = w & 511;
            int trow = w2 >> 3, cch = w2 & 7;
            const __half* src = (buf ? Klo : Khi) +
                (size_t)(tok0 + trow) * (KVH * HD) + kh * HD + half_ * 64 + cch * 8;
            uint32_t dst = sbm + (buf ? ATT_KLO : ATT_KHI) + half_ * 8192 + swoff(trow, cch);
            cp_async16(dst, src);
        }
#pragma unroll
        for (int t = 0; t < 8; t++) {
            int id = tid + t * 256;
            int buf = id >> 10;
            int w = id & 1023;
            int drow = w >> 3, cch = w & 7;
            int half_ = drow >> 6, rl = drow & 63;
            const __half* src = (buf ? Vtlo : Vthi) +
                ((size_t)kh * HD + drow) * T_TOK + tok0 + cch * 8;
            uint32_t dst = sbm + (buf ? ATT_VLO : ATT_VHI) + half_ * 8192 + swoff(rl, cch);
            cp_async16(dst, src);
        }
        cp_commit();
        cp_wait<0>();
        __syncthreads();

        // ---- QK^T (3-pass) ----
        float sacc[4][4];
#pragma unroll
        for (int i = 0; i < 4; i++)
#pragma unroll
            for (int j = 0; j < 4; j++) sacc[i][j] = 0.0f;

#pragma unroll
        for (int half_ = 0; half_ < 2; half_++) {
#pragma unroll
            for (int s4 = 0; s4 < 4; s4++) {
                uint32_t offa = half_ * 8192 + swoff(a_row, (s4 << 1) + a_csel);
                uint32_t ah4[4], al4[4];
                ldsm4(ah4, sbm + ATT_QHI + offa);
                ldsm4(al4, sbm + ATT_QLO + offa);
                uint32_t bh[2][4], bl[2][4];
#pragma unroll
                for (int jb = 0; jb < 2; jb++) {
                    uint32_t offb = half_ * 8192 + swoff(b_row + jb * 16, (s4 << 1) + b_csel);
                    ldsm4(bh[jb], sbm + ATT_KHI + offb);
                    ldsm4(bl[jb], sbm + ATT_KLO + offb);
                }
#pragma unroll
                for (int nj = 0; nj < 4; nj++) {
                    const uint32_t* ph = &bh[nj >> 1][(nj & 1) * 2];
                    const uint32_t* pl = &bl[nj >> 1][(nj & 1) * 2];
                    mma16816(sacc[nj], ah4, ph);
                    mma16816(sacc[nj], ah4, pl);
                    mma16816(sacc[nj], al4, ph);
                }
            }
        }

        // ---- write S with scale + causal mask ----
        const bool diag = (kb == qb_local);
#pragma unroll
        for (int nj = 0; nj < 4; nj++) {
            int mloc = warp_m * 16 + qrow;
            int cloc = warp_n * 32 + nj * 8 + qcol;
            float v0 = sacc[nj][0] * SCALE;
            float v1 = sacc[nj][1] * SCALE;
            float v2 = sacc[nj][2] * SCALE;
            float v3 = sacc[nj][3] * SCALE;
            if (diag) {
                if (cloc     > mloc)     v0 = -1e30f;
                if (cloc + 1 > mloc)     v1 = -1e30f;
                if (cloc     > mloc + 8) v2 = -1e30f;
                if (cloc + 1 > mloc + 8) v3 = -1e30f;
            }
            Ss[mloc * 68 + cloc]           = v0;
            Ss[mloc * 68 + cloc + 1]       = v1;
            Ss[(mloc + 8) * 68 + cloc]     = v2;
            Ss[(mloc + 8) * 68 + cloc + 1] = v3;
        }
        __syncthreads();

        // ---- online softmax (4 threads/row), P -> fp16 swizzled ----
        {
            float lmax = -INFINITY;
            int base = srow * 68 + sq * 16;
#pragma unroll
            for (int jj = 0; jj < 16; jj++)
                lmax = fmaxf(lmax, Ss[base + jj]);
            lmax = fmaxf(lmax, __shfl_xor_sync(0xffffffffu, lmax, 1));
            lmax = fmaxf(lmax, __shfl_xor_sync(0xffffffffu, lmax, 2));
            float m_new = fmaxf(m_run, lmax);
            float alpha = __expf(m_run - m_new);
            float lsum = 0.0f;
#pragma unroll
            for (int jj = 0; jj < 16; jj += 2) {
                float p0 = __expf(Ss[base + jj] - m_new);
                float p1 = __expf(Ss[base + jj + 1] - m_new);
                lsum += p0 + p1;
                int col = sq * 16 + jj;
                uint32_t byte = (uint32_t)(srow * 128) +
                    ((((col >> 3)) ^ (srow & 7)) << 4) + (col & 7) * 2;
                *(__half2*)(smc + ATT_PS + byte) = __floats2half2_rn(p0, p1);
            }
            lsum += __shfl_xor_sync(0xffffffffu, lsum, 1);
            lsum += __shfl_xor_sync(0xffffffffu, lsum, 2);
            l_run = l_run * alpha + lsum;
            m_run = m_new;
            if ((tid & 3) == 0) { alphas[srow] = alpha; lrow[srow] = l_run; }
        }
        __syncthreads();

        // ---- PV: o = o*alpha + P @ V (2-pass on V) ----
        {
            float a0 = alphas[warp_m * 16 + qrow];
            float a1 = alphas[warp_m * 16 + qrow + 8];
#pragma unroll
            for (int nj = 0; nj < 8; nj++) {
                o[nj][0] *= a0; o[nj][1] *= a0;
                o[nj][2] *= a1; o[nj][3] *= a1;
            }
#pragma unroll
            for (int s4 = 0; s4 < 4; s4++) {
                uint32_t ap[4];
                ldsm4(ap, sbm + ATT_PS + swoff(a_row, (s4 << 1) + a_csel));
                uint32_t vh[4][4], vl[4][4];
#pragma unroll
                for (int nb = 0; nb < 4; nb++) {
                    uint32_t offv = warp_n * 8192 +
                        swoff(pb_row + nb * 16, (s4 << 1) + b_csel);
                    ldsm4(vh[nb], sbm + ATT_VHI + offv);
                    ldsm4(vl[nb], sbm + ATT_VLO + offv);
                }
#pragma unroll
                for (int nj = 0; nj < 8; nj++) {
                    const uint32_t* ph = &vh[nj >> 1][(nj & 1) * 2];
                    const uint32_t* pl = &vl[nj >> 1][(nj & 1) * 2];
                    mma16816(o[nj], ap, ph);
                    mma16816(o[nj], ap, pl);
                }
            }
        }
        __syncthreads();   // protect K/V/P smem before next iteration's loads
    }

    // ---- epilogue: normalize, write fp16 O (A operand of O-proj) ----
    float inv0 = 1.0f / lrow[warp_m * 16 + qrow];
    float inv1 = 1.0f / lrow[warp_m * 16 + qrow + 8];
#pragma unroll
    for (int nj = 0; nj < 8; nj++) {
        int m = q_start + warp_m * 16 + qrow;
        int col = h * HD + warp_n * 64 + nj * 8 + qcol;
        *(__half2*)(oh + (size_t)m * DM + col) =
            __floats2half2_rn(o[nj][0] * inv0, o[nj][1] * inv0);
        *(__half2*)(oh + (size_t)(m + 8) * DM + col) =
            __floats2half2_rn(o[nj][2] * inv1, o[nj][3] * inv1);
    }
}

// ============================================================================
// launch
// ============================================================================
extern "C" void kernel_launch(void* const* d_in, const int* in_sizes, int n_in,
                              void* d_out, int out_size)
{
    const float* hs    = (const float*)d_in[0];
    const float* w_qkv = (const float*)d_in[1];
    const float* w_o   = (const float*)d_in[2];
    const float* cs    = (const float*)d_in[3];
    const float* sn    = (const float*)d_in[4];
    (void)in_sizes; (void)n_in;

    float* qkv_buf = nullptr;
    __half *ah, *bhi, *blo, *qhi, *qlo, *khi, *klo, *vthi, *vtlo;
    cudaGetSymbolAddress((void**)&qkv_buf, g_qkv);
    cudaGetSymbolAddress((void**)&ah, g_ah);
    cudaGetSymbolAddress((void**)&bhi, g_bhi);
    cudaGetSymbolAddress((void**)&blo, g_blo);
    cudaGetSymbolAddress((void**)&qhi, g_qhi);
    cudaGetSymbolAddress((void**)&qlo, g_qlo);
    cudaGetSymbolAddress((void**)&khi, g_khi);
    cudaGetSymbolAddress((void**)&klo, g_klo);
    cudaGetSymbolAddress((void**)&vthi, g_vthi);
    cudaGetSymbolAddress((void**)&vtlo, g_vtlo);

    static int attr_set = 0;
    if (!attr_set) {
        cudaFuncSetAttribute(attn_kernel, cudaFuncAttributeMaxDynamicSharedMemorySize,
                             ATT_SMEM);
        cudaFuncSetAttribute(gemm_tc_kernel, cudaFuncAttributeMaxDynamicSharedMemorySize,
                             GEMM_SMEM);
        attr_set = 1;
    }

    // convert A, split B
    cvt_half_kernel<<<(T_TOK * DM / 4) / 256, 256>>>(hs, ah, T_TOK * DM / 4);
    split_kernel<<<(QKV_N * DM / 4) / 256, 256>>>(w_qkv, bhi, blo, QKV_N * DM / 4);

    // QKV projection + clip
    gemm_tc_kernel<<<dim3(QKV_N / 128, T_TOK / 128), 256, GEMM_SMEM>>>(
        ah, bhi, blo, qkv_buf, QKV_N, 1);

    // RoPE -> fp16 hi/lo Q,K ; V transpose -> fp16 hi/lo
    rope_kernel<<<dim3(T_TOK, 10), 256>>>(qkv_buf, cs, sn, qhi, qlo, khi, klo);
    vtrans_kernel<<<dim3(T_TOK / 64, KVH), 256>>>(qkv_buf, vthi, vtlo);

    // tensor-core flash attention -> fp16 O into g_ah
    attn_kernel<<<dim3(32, NH), 256, ATT_SMEM>>>(qhi, qlo, khi, klo, vthi, vtlo, ah);

    // split w_o, then output projection
    split_kernel<<<(DM * DM / 4) / 256, 256>>>(w_o, bhi, blo, DM * DM / 4);

    gemm_tc_kernel<<<dim3(DM / 128, T_TOK / 128), 256, GEMM_SMEM>>>(
        ah, bhi, blo, (float*)d_out, DM, 0);
}